// round 8
// baseline (speedup 1.0000x reference)
#include <cuda_runtime.h>
#include <cuda_fp16.h>
#include <cuda_bf16.h>
#include <math.h>
#include <cstdint>

// Problem constants
#define T_TOK 2048
#define HID   4096
#define NH    32
#define NKV   8
#define HD    128
#define QKV_W ((NH + 2*NKV) * HD)   // 6144
#define OUT_W (NH * HD)             // 4096
#define SM_SCALE 0.08838834764831843f  // 1/sqrt(128)

// ---------------------------------------------------------------------------
// Scratch (allocation-free -> device globals), all 16B-aligned for cp.async
// ---------------------------------------------------------------------------
__device__ __align__(16) float    g_qkv[(size_t)T_TOK * QKV_W];
__device__ __align__(16) unsigned g_Qh[(size_t)T_TOK * 2048];
__device__ __align__(16) unsigned g_Ql[(size_t)T_TOK * 2048];
__device__ __align__(16) unsigned g_Kh[(size_t)T_TOK * 512];
__device__ __align__(16) unsigned g_Kl[(size_t)T_TOK * 512];
__device__ __align__(16) unsigned g_VTh[(size_t)NKV * HD * (T_TOK/2)];
__device__ __align__(16) unsigned g_VTl[(size_t)NKV * HD * (T_TOK/2)];
__device__ __align__(16) __half   g_h16[(size_t)T_TOK * HID];
__device__ __align__(16) __half   g_wqkv16[(size_t)HID * QKV_W];
__device__ __align__(16) __half   g_wo16[(size_t)OUT_W * HID];
__device__ __align__(16) __half   g_attn16[(size_t)T_TOK * OUT_W];
__device__ float g_invfreq_pi[HD/2];

// ---------------------------------------------------------------------------
// helpers
// ---------------------------------------------------------------------------
__device__ __forceinline__ unsigned packh2(float x, float y) {
    __half2 h = __floats2half2_rn(x, y);
    return *(unsigned*)&h;
}

__device__ __forceinline__ void split2(float x, float y, unsigned& hi, unsigned& lo) {
    __half hx = __float2half_rn(x);
    __half hy = __float2half_rn(y);
    float rx = x - __half2float(hx);
    float ry = y - __half2float(hy);
    hi = (unsigned)__half_as_ushort(hx) | ((unsigned)__half_as_ushort(hy) << 16);
    lo = (unsigned)__half_as_ushort(__float2half_rn(rx)) |
         ((unsigned)__half_as_ushort(__float2half_rn(ry)) << 16);
}

__device__ __forceinline__ void mma16(float c[4], unsigned a0, unsigned a1,
                                      unsigned a2, unsigned a3,
                                      unsigned b0, unsigned b1) {
    asm volatile(
        "mma.sync.aligned.m16n8k16.row.col.f32.f16.f16.f32 "
        "{%0,%1,%2,%3}, {%4,%5,%6,%7}, {%8,%9}, {%0,%1,%2,%3};\n"
        : "+f"(c[0]), "+f"(c[1]), "+f"(c[2]), "+f"(c[3])
        : "r"(a0), "r"(a1), "r"(a2), "r"(a3), "r"(b0), "r"(b1));
}

__device__ __forceinline__ unsigned smem_u32(const void* p) {
    return (unsigned)__cvta_generic_to_shared(p);
}

__device__ __forceinline__ void ldsm_x4(unsigned& r0, unsigned& r1,
                                        unsigned& r2, unsigned& r3,
                                        unsigned addr) {
    asm volatile("ldmatrix.sync.aligned.m8n8.x4.shared.b16 {%0,%1,%2,%3}, [%4];\n"
                 : "=r"(r0), "=r"(r1), "=r"(r2), "=r"(r3) : "r"(addr));
}

__device__ __forceinline__ void ldsm_x4_t(unsigned& r0, unsigned& r1,
                                          unsigned& r2, unsigned& r3,
                                          unsigned addr) {
    asm volatile("ldmatrix.sync.aligned.m8n8.x4.trans.shared.b16 {%0,%1,%2,%3}, [%4];\n"
                 : "=r"(r0), "=r"(r1), "=r"(r2), "=r"(r3) : "r"(addr));
}

#define CP16(dst, src) \
    asm volatile("cp.async.cg.shared.global [%0], [%1], 16;\n" \
                 :: "r"(dst), "l"(src))
#define CP16A(dst, src) \
    asm volatile("cp.async.ca.shared.global [%0], [%1], 16;\n" \
                 :: "r"(dst), "l"(src))
#define CPCOMMIT() asm volatile("cp.async.commit_group;\n")
#define CPWAIT0()  asm volatile("cp.async.wait_group 0;\n")
#define CPWAIT1()  asm volatile("cp.async.wait_group 1;\n")

// ---------------------------------------------------------------------------
// small kernels
// ---------------------------------------------------------------------------
__global__ void init_invfreq_kernel() {
    int i = threadIdx.x;
    double inv = pow(1.0e6, -((double)(2 * i)) / 128.0);
    g_invfreq_pi[i] = (float)(inv / 3.14159265358979323846);
}

__global__ void conv_f16_kernel(const float4* __restrict__ src,
                                uint2* __restrict__ dst, int n4) {
    int i = blockIdx.x * blockDim.x + threadIdx.x;
    if (i < n4) {
        float4 v = src[i];
        dst[i] = make_uint2(packh2(v.x, v.y), packh2(v.z, v.w));
    }
}

// RoPE + scale + hi/lo split for Q and K heads -> global half2 planes
__global__ void prep_qk_kernel(const int* __restrict__ positions,
                               const float* __restrict__ qkv) {
    int t = blockIdx.x;
    int h = blockIdx.y;
    int i = threadIdx.x;
    float pos = (float)positions[t];
    float f = pos * g_invfreq_pi[i];
    float c = cospif(f);
    float s = sinpif(f);
    const float* base = qkv + (size_t)t * QKV_W + h * HD;
    float x1 = base[2 * i];
    float x2 = base[2 * i + 1];
    float o1 = x1 * c - x2 * s;
    float o2 = x2 * c + x1 * s;
    unsigned hi, lo;
    if (h < NH) {
        o1 *= SM_SCALE;
        o2 *= SM_SCALE;
        split2(o1, o2, hi, lo);
        g_Qh[(size_t)t * 2048 + h * 64 + i] = hi;
        g_Ql[(size_t)t * 2048 + h * 64 + i] = lo;
    } else {
        int kh = h - NH;
        split2(o1, o2, hi, lo);
        g_Kh[(size_t)t * 512 + kh * 64 + i] = hi;
        g_Kl[(size_t)t * 512 + kh * 64 + i] = lo;
    }
}

// V split + transpose: VT[hk][d][token-pair word]
__global__ __launch_bounds__(256) void prep_v_kernel(const float* __restrict__ qkv) {
    __shared__ float Vs[64 * 133];
    int bt = blockIdx.x;
    int hk = blockIdx.y;
    int tid = threadIdx.x;
    const float* vb = qkv + (size_t)bt * 64 * QKV_W + (NH + NKV) * HD + hk * HD;
#pragma unroll
    for (int it = 0; it < 8; it++) {
        int idx = tid + it * 256;
        int r = idx >> 5;
        int c4 = (idx & 31) * 4;
        float4 v = *(const float4*)(vb + (size_t)r * QKV_W + c4);
        Vs[r * 133 + c4 + 0] = v.x;
        Vs[r * 133 + c4 + 1] = v.y;
        Vs[r * 133 + c4 + 2] = v.z;
        Vs[r * 133 + c4 + 3] = v.w;
    }
    __syncthreads();
#pragma unroll
    for (int it = 0; it < 16; it++) {
        int d = it * 8 + (tid >> 5);
        int jw = tid & 31;
        float v0 = Vs[(2 * jw) * 133 + d];
        float v1 = Vs[(2 * jw + 1) * 133 + d];
        unsigned hi, lo;
        split2(v0, v1, hi, lo);
        size_t w = (size_t)(hk * 128 + d) * (T_TOK / 2) + bt * 32 + jw;
        g_VTh[w] = hi;
        g_VTl[w] = lo;
    }
}

// ---------------------------------------------------------------------------
// fp16 HGEMM v2: C[M,N] f32 = A[M,K]h @ B[K,N]h, row-major.
// Block tile 128(M) x 256(N), BK=32, 8 warps (2x4 -> 64x64 per warp),
// 3-stage cp.async pipeline, ldmatrix fragments.
// M mult of 128, N mult of 256, K mult of 32.
// ---------------------------------------------------------------------------
#define GA_STR 40     // halves per A smem row (32+8)
#define GB_STR 264    // halves per B smem row (256+8): 528B = 1 chunk mod 8 rows

#define HG_A_BYTES (128 * GA_STR * 2)   // 10240
#define HG_B_BYTES (32 * GB_STR * 2)    // 16896
#define HG_STAGE_BYTES (HG_A_BYTES + HG_B_BYTES)
#define HG_SMEM_BYTES (3 * HG_STAGE_BYTES)   // 81408

__global__ __launch_bounds__(256) void hgemm(const __half* __restrict__ A,
                                             const __half* __restrict__ B,
                                             float* __restrict__ C,
                                             int M, int N, int K) {
    extern __shared__ char hsm[];
    __half* As[3];
    __half* Bs[3];
#pragma unroll
    for (int s = 0; s < 3; s++) {
        As[s] = (__half*)(hsm + s * HG_STAGE_BYTES);
        Bs[s] = (__half*)(hsm + s * HG_STAGE_BYTES + HG_A_BYTES);
    }

    int tid = threadIdx.x;
    int warp = tid >> 5;
    int lane = tid & 31;
    int wm = warp >> 2;            // 0..1
    int wn = warp & 3;             // 0..3
    int m_warp = wm * 64;
    int n_warp = wn * 64;
    int gid = lane >> 2;
    int tig = lane & 3;
    int lrow = (lane & 7) + ((lane >> 3) & 1) * 8;
    int lcol8 = (lane >> 4) * 8;

    const __half* Ab = A + (size_t)blockIdx.y * 128 * K;
    const __half* Bb = B + (size_t)blockIdx.x * 256;
    float* Cb = C + (size_t)blockIdx.y * 128 * N + (size_t)blockIdx.x * 256;

    float acc[4][8][4];
#pragma unroll
    for (int mt = 0; mt < 4; mt++)
#pragma unroll
        for (int ng = 0; ng < 8; ng++)
#pragma unroll
            for (int q = 0; q < 4; q++) acc[mt][ng][q] = 0.f;

    // stage one BK=32 chunk into stage s
    auto stage = [&](int s, int k0) {
        // A: 128 x 32 halves = 512 cp16
#pragma unroll
        for (int it = 0; it < 2; it++) {
            int idx = tid + it * 256;          // 0..511
            int r = idx >> 2;                  // 0..127
            int c8 = (idx & 3) * 8;            // 0..24
            CP16(smem_u32(As[s] + r * GA_STR + c8),
                 Ab + (size_t)r * K + k0 + c8);
        }
        // B: 32 x 256 halves = 1024 cp16
#pragma unroll
        for (int it = 0; it < 4; it++) {
            int idx = tid + it * 256;          // 0..1023
            int r = idx >> 5;                  // 0..31
            int c8 = (idx & 31) * 8;           // 0..248
            CP16(smem_u32(Bs[s] + r * GB_STR + c8),
                 Bb + (size_t)(k0 + r) * N + c8);
        }
        CPCOMMIT();
    };

    int NC = K / 32;
    stage(0, 0);
    stage(1, 32);

    for (int i = 0; i < NC; i++) {
        int s = i % 3;
        CPWAIT1();
        __syncthreads();

        const __half* Ac = As[s];
        const __half* Bc = Bs[s];
#pragma unroll
        for (int ks = 0; ks < 32; ks += 16) {
            unsigned bf[4][4];
#pragma unroll
            for (int nt = 0; nt < 4; nt++) {
                ldsm_x4_t(bf[nt][0], bf[nt][1], bf[nt][2], bf[nt][3],
                          smem_u32(Bc + (ks + lrow) * GB_STR + n_warp + nt * 16 + lcol8));
            }
#pragma unroll
            for (int mt = 0; mt < 4; mt++) {
                unsigned a0, a1, a2, a3;
                ldsm_x4(a0, a1, a2, a3,
                        smem_u32(Ac + (m_warp + mt * 16 + lrow) * GA_STR + ks + lcol8));
#pragma unroll
                for (int nt = 0; nt < 4; nt++) {
                    mma16(acc[mt][2 * nt],     a0, a1, a2, a3, bf[nt][0], bf[nt][1]);
                    mma16(acc[mt][2 * nt + 1], a0, a1, a2, a3, bf[nt][2], bf[nt][3]);
                }
            }
        }

        if (i + 2 < NC) stage((i + 2) % 3, (i + 2) * 32);
    }

    // epilogue
#pragma unroll
    for (int mt = 0; mt < 4; mt++) {
#pragma unroll
        for (int ng = 0; ng < 8; ng++) {
            int row0 = m_warp + mt * 16 + gid;
            int col  = n_warp + ng * 8 + tig * 2;
            *(float2*)(Cb + (size_t)row0 * N + col) =
                make_float2(acc[mt][ng][0], acc[mt][ng][1]);
            *(float2*)(Cb + (size_t)(row0 + 8) * N + col) =
                make_float2(acc[mt][ng][2], acc[mt][ng][3]);
        }
    }
}

// ---------------------------------------------------------------------------
// Flash attention: precomputed split planes, cp.async staging, ldmatrix.
// (unchanged from round 5 passing build)
// ---------------------------------------------------------------------------
#define QK_STR 68
#define VT_STR 36
#define PH_STR 36

#define QH0_OFF 0
#define QH1_OFF (128*QK_STR)
#define KH0_OFF (QH1_OFF + 128*QK_STR)
#define KH1_OFF (KH0_OFF + 64*QK_STR)
#define VT0_OFF (KH1_OFF + 64*QK_STR)
#define VT1_OFF (VT0_OFF + 128*VT_STR)
#define PH0_OFF (VT1_OFF + 128*VT_STR)
#define PH1_OFF (PH0_OFF + 128*PH_STR)
#define FLASH_SMEM_WORDS (PH1_OFF + 128*PH_STR)
#define FLASH_SMEM_BYTES (FLASH_SMEM_WORDS * 4)

__global__ __launch_bounds__(256) void flash16_kernel(__half* __restrict__ out16) {
    extern __shared__ unsigned sw[];
    unsigned* QH0 = sw + QH0_OFF;
    unsigned* QH1 = sw + QH1_OFF;
    unsigned* KH0 = sw + KH0_OFF;
    unsigned* KH1 = sw + KH1_OFF;
    unsigned* VT0 = sw + VT0_OFF;
    unsigned* VT1 = sw + VT1_OFF;
    unsigned* PH0 = sw + PH0_OFF;
    unsigned* PH1 = sw + PH1_OFF;

    int qb = gridDim.x - 1 - blockIdx.x;
    int hq = blockIdx.y;
    int hk = hq >> 2;
    int tid = threadIdx.x;
    int warp = tid >> 5;
    int lane = tid & 31;
    int gid = lane >> 2;
    int tig = lane & 3;
    int m0 = warp * 16;

    int lrow  = (lane & 7) + ((lane >> 3) & 1) * 8;
    int acol4 = ((lane >> 4) & 1) * 4;
    int krow  = (lane & 7) + ((lane >> 4) & 1) * 8;
    int kcol4 = ((lane >> 3) & 1) * 4;

#pragma unroll
    for (int it = 0; it < 8; it++) {
        int idx = tid + it * 256;
        int r = idx >> 4;
        int c = (idx & 15) * 4;
        const unsigned* s0 = g_Qh + (size_t)(qb * 128 + r) * 2048 + hq * 64 + c;
        const unsigned* s1 = g_Ql + (size_t)(qb * 128 + r) * 2048 + hq * 64 + c;
        CP16A(smem_u32(QH0 + r * QK_STR + c), s0);
        CP16A(smem_u32(QH1 + r * QK_STR + c), s1);
    }

    float mprev0 = -1e30f, mprev1 = -1e30f;
    float lsum0 = 0.f, lsum1 = 0.f;
    float acco[16][4];
#pragma unroll
    for (int dt = 0; dt < 16; dt++)
#pragma unroll
        for (int q = 0; q < 4; q++) acco[dt][q] = 0.f;

    int grow0 = qb * 128 + m0 + gid;
    int grow1 = grow0 + 8;

    int nkt = 2 * qb + 2;
    for (int kt = 0; kt < nkt; kt++) {
        __syncthreads();

#pragma unroll
        for (int it = 0; it < 4; it++) {
            int idx = tid + it * 256;
            int r = idx >> 4;
            int c = (idx & 15) * 4;
            const unsigned* s0 = g_Kh + (size_t)(kt * 64 + r) * 512 + hk * 64 + c;
            const unsigned* s1 = g_Kl + (size_t)(kt * 64 + r) * 512 + hk * 64 + c;
            CP16A(smem_u32(KH0 + r * QK_STR + c), s0);
            CP16A(smem_u32(KH1 + r * QK_STR + c), s1);
        }
#pragma unroll
        for (int it = 0; it < 4; it++) {
            int idx = tid + it * 256;
            int r = idx >> 3;
            int c = (idx & 7) * 4;
            const unsigned* s0 = g_VTh + (size_t)(hk * 128 + r) * (T_TOK/2) + kt * 32 + c;
            const unsigned* s1 = g_VTl + (size_t)(hk * 128 + r) * (T_TOK/2) + kt * 32 + c;
            CP16A(smem_u32(VT0 + r * VT_STR + c), s0);
            CP16A(smem_u32(VT1 + r * VT_STR + c), s1);
        }
        CPCOMMIT();
        CPWAIT0();
        __syncthreads();

        float accs[8][4];
#pragma unroll
        for (int nt = 0; nt < 8; nt++)
#pragma unroll
            for (int q = 0; q < 4; q++) accs[nt][q] = 0.f;

#pragma unroll
        for (int ks = 0; ks < 8; ks++) {
            unsigned ah[4], al[4];
            ldsm_x4(ah[0], ah[1], ah[2], ah[3],
                    smem_u32(QH0 + (m0 + lrow) * QK_STR + ks * 8 + acol4));
            ldsm_x4(al[0], al[1], al[2], al[3],
                    smem_u32(QH1 + (m0 + lrow) * QK_STR + ks * 8 + acol4));
#pragma unroll
            for (int nt2 = 0; nt2 < 4; nt2++) {
                unsigned bh[4], bl[4];
                ldsm_x4(bh[0], bh[1], bh[2], bh[3],
                        smem_u32(KH0 + (nt2 * 16 + krow) * QK_STR + ks * 8 + kcol4));
                ldsm_x4(bl[0], bl[1], bl[2], bl[3],
                        smem_u32(KH1 + (nt2 * 16 + krow) * QK_STR + ks * 8 + kcol4));
                mma16(accs[2*nt2],   ah[0], ah[1], ah[2], ah[3], bh[0], bh[1]);
                mma16(accs[2*nt2],   ah[0], ah[1], ah[2], ah[3], bl[0], bl[1]);
                mma16(accs[2*nt2],   al[0], al[1], al[2], al[3], bh[0], bh[1]);
                mma16(accs[2*nt2+1], ah[0], ah[1], ah[2], ah[3], bh[2], bh[3]);
                mma16(accs[2*nt2+1], ah[0], ah[1], ah[2], ah[3], bl[2], bl[3]);
                mma16(accs[2*nt2+1], al[0], al[1], al[2], al[3], bh[2], bh[3]);
            }
        }

        int colb = kt * 64 + 2 * tig;
        float mx0 = -1e30f, mx1 = -1e30f;
#pragma unroll
        for (int nt = 0; nt < 8; nt++) {
            int c0 = colb + nt * 8;
            int c1 = c0 + 1;
            accs[nt][0] = (c0 <= grow0) ? accs[nt][0] : -1e30f;
            accs[nt][1] = (c1 <= grow0) ? accs[nt][1] : -1e30f;
            accs[nt][2] = (c0 <= grow1) ? accs[nt][2] : -1e30f;
            accs[nt][3] = (c1 <= grow1) ? accs[nt][3] : -1e30f;
            mx0 = fmaxf(mx0, fmaxf(accs[nt][0], accs[nt][1]));
            mx1 = fmaxf(mx1, fmaxf(accs[nt][2], accs[nt][3]));
        }
        mx0 = fmaxf(mx0, __shfl_xor_sync(0xffffffffu, mx0, 1));
        mx0 = fmaxf(mx0, __shfl_xor_sync(0xffffffffu, mx0, 2));
        mx1 = fmaxf(mx1, __shfl_xor_sync(0xffffffffu, mx1, 1));
        mx1 = fmaxf(mx1, __shfl_xor_sync(0xffffffffu, mx1, 2));

        float mn0 = fmaxf(mprev0, mx0);
        float mn1 = fmaxf(mprev1, mx1);
        float corr0 = __expf(mprev0 - mn0);
        float corr1 = __expf(mprev1 - mn1);
        mprev0 = mn0;
        mprev1 = mn1;

        float sum0 = 0.f, sum1 = 0.f;
#pragma unroll
        for (int nt = 0; nt < 8; nt++) {
            accs[nt][0] = __expf(accs[nt][0] - mn0);
            accs[nt][1] = __expf(accs[nt][1] - mn0);
            accs[nt][2] = __expf(accs[nt][2] - mn1);
            accs[nt][3] = __expf(accs[nt][3] - mn1);
            sum0 += accs[nt][0] + accs[nt][1];
            sum1 += accs[nt][2] + accs[nt][3];
        }
        sum0 += __shfl_xor_sync(0xffffffffu, sum0, 1);
        sum0 += __shfl_xor_sync(0xffffffffu, sum0, 2);
        sum1 += __shfl_xor_sync(0xffffffffu, sum1, 1);
        sum1 += __shfl_xor_sync(0xffffffffu, sum1, 2);
        lsum0 = lsum0 * corr0 + sum0;
        lsum1 = lsum1 * corr1 + sum1;

#pragma unroll
        for (int dt = 0; dt < 16; dt++) {
            acco[dt][0] *= corr0;
            acco[dt][1] *= corr0;
            acco[dt][2] *= corr1;
            acco[dt][3] *= corr1;
        }

#pragma unroll
        for (int nt = 0; nt < 8; nt++) {
            unsigned hi0, lo0, hi1, lo1;
            split2(accs[nt][0], accs[nt][1], hi0, lo0);
            split2(accs[nt][2], accs[nt][3], hi1, lo1);
            int w0 = (m0 + gid) * PH_STR + nt * 4 + tig;
            int w1 = (m0 + gid + 8) * PH_STR + nt * 4 + tig;
            PH0[w0] = hi0;
            PH1[w0] = lo0;
            PH0[w1] = hi1;
            PH1[w1] = lo1;
        }
        __syncwarp();

#pragma unroll
        for (int ks = 0; ks < 4; ks++) {
            unsigned ah[4], al[4];
            ldsm_x4(ah[0], ah[1], ah[2], ah[3],
                    smem_u32(PH0 + (m0 + lrow) * PH_STR + ks * 8 + acol4));
            ldsm_x4(al[0], al[1], al[2], al[3],
                    smem_u32(PH1 + (m0 + lrow) * PH_STR + ks * 8 + acol4));
#pragma unroll
            for (int dt2 = 0; dt2 < 8; dt2++) {
                unsigned vh[4], vl[4];
                ldsm_x4(vh[0], vh[1], vh[2], vh[3],
                        smem_u32(VT0 + (dt2 * 16 + krow) * VT_STR + ks * 8 + kcol4));
                ldsm_x4(vl[0], vl[1], vl[2], vl[3],
                        smem_u32(VT1 + (dt2 * 16 + krow) * VT_STR + ks * 8 + kcol4));
                mma16(acco[2*dt2],   ah[0], ah[1], ah[2], ah[3], vh[0], vh[1]);
                mma16(acco[2*dt2],   ah[0], ah[1], ah[2], ah[3], vl[0], vl[1]);
                mma16(acco[2*dt2],   al[0], al[1], al[2], al[3], vh[0], vh[1]);
                mma16(acco[2*dt2+1], ah[0], ah[1], ah[2], ah[3], vh[2], vh[3]);
                mma16(acco[2*dt2+1], ah[0], ah[1], ah[2], ah[3], vl[2], vl[3]);
                mma16(acco[2*dt2+1], al[0], al[1], al[2], al[3], vh[2], vh[3]);
            }
        }
    }

    float il0 = 1.0f / lsum0;
    float il1 = 1.0f / lsum1;
    __half* o0 = out16 + (size_t)grow0 * OUT_W + hq * HD;
    __half* o1 = out16 + (size_t)grow1 * OUT_W + hq * HD;
#pragma unroll
    for (int dt = 0; dt < 16; dt++) {
        int col = dt * 8 + 2 * tig;
        *(unsigned*)(o0 + col) = packh2(acco[dt][0] * il0, acco[dt][1] * il0);
        *(unsigned*)(o1 + col) = packh2(acco[dt][2] * il1, acco[dt][3] * il1);
    }
}

// ---------------------------------------------------------------------------
// launch
// ---------------------------------------------------------------------------
extern "C" void kernel_launch(void* const* d_in, const int* in_sizes, int n_in,
                              void* d_out, int out_size) {
    (void)in_sizes; (void)n_in; (void)out_size;
    const int*   positions = (const int*)d_in[0];
    const float* hidden    = (const float*)d_in[1];
    const float* Wqkv      = (const float*)d_in[2];
    const float* Wo        = (const float*)d_in[3];
    float*       out       = (float*)d_out;

    void *qkv_p, *h16_p, *wqkv16_p, *wo16_p, *attn16_p;
    cudaGetSymbolAddress(&qkv_p, g_qkv);
    cudaGetSymbolAddress(&h16_p, g_h16);
    cudaGetSymbolAddress(&wqkv16_p, g_wqkv16);
    cudaGetSymbolAddress(&wo16_p, g_wo16);
    cudaGetSymbolAddress(&attn16_p, g_attn16);
    float*  qkv    = (float*)qkv_p;
    __half* h16    = (__half*)h16_p;
    __half* wqkv16 = (__half*)wqkv16_p;
    __half* wo16   = (__half*)wo16_p;
    __half* attn16 = (__half*)attn16_p;

    cudaFuncSetAttribute(flash16_kernel,
                         cudaFuncAttributeMaxDynamicSharedMemorySize,
                         FLASH_SMEM_BYTES);
    cudaFuncSetAttribute(hgemm,
                         cudaFuncAttributeMaxDynamicSharedMemorySize,
                         HG_SMEM_BYTES);

    init_invfreq_kernel<<<1, 64>>>();

    // fp32 -> fp16 conversions
    {
        int n4 = T_TOK * HID / 4;
        conv_f16_kernel<<<(n4 + 255) / 256, 256>>>((const float4*)hidden,
                                                   (uint2*)h16, n4);
        n4 = HID * QKV_W / 4;
        conv_f16_kernel<<<(n4 + 255) / 256, 256>>>((const float4*)Wqkv,
                                                   (uint2*)wqkv16, n4);
        n4 = OUT_W * HID / 4;
        conv_f16_kernel<<<(n4 + 255) / 256, 256>>>((const float4*)Wo,
                                                   (uint2*)wo16, n4);
    }

    // qkv = hidden @ Wqkv
    hgemm<<<dim3(QKV_W / 256, T_TOK / 128), 256, HG_SMEM_BYTES>>>(
        h16, wqkv16, qkv, T_TOK, QKV_W, HID);

    // RoPE + split planes; V split + transpose
    prep_qk_kernel<<<dim3(T_TOK, NH + NKV), 64>>>(positions, qkv);
    prep_v_kernel<<<dim3(T_TOK / 64, NKV), 256>>>(qkv);

    // flash attention
    flash16_kernel<<<dim3(T_TOK / 128, NH), 256, FLASH_SMEM_BYTES>>>(attn16);

    // out = attn @ Wo
    hgemm<<<dim3(HID / 256, T_TOK / 128), 256, HG_SMEM_BYTES>>>(
        attn16, wo16, out, T_TOK, HID, HID);
}

// round 9
// speedup vs baseline: 1.0311x; 1.0311x over previous
#include <cuda_runtime.h>
#include <cuda_fp16.h>
#include <cuda_bf16.h>
#include <math.h>
#include <cstdint>

// Problem constants
#define T_TOK 2048
#define HID   4096
#define NH    32
#define NKV   8
#define HD    128
#define QKV_W ((NH + 2*NKV) * HD)   // 6144
#define OUT_W (NH * HD)             // 4096
#define SM_SCALE 0.08838834764831843f  // 1/sqrt(128)

// ---------------------------------------------------------------------------
// Scratch (allocation-free -> device globals), all 16B-aligned for cp.async
// ---------------------------------------------------------------------------
__device__ __align__(16) float    g_qkv[(size_t)T_TOK * QKV_W];
__device__ __align__(16) unsigned g_Qh[(size_t)T_TOK * 2048];
__device__ __align__(16) unsigned g_Ql[(size_t)T_TOK * 2048];
__device__ __align__(16) unsigned g_Kh[(size_t)T_TOK * 512];
__device__ __align__(16) unsigned g_Kl[(size_t)T_TOK * 512];
__device__ __align__(16) unsigned g_VTh[(size_t)NKV * HD * (T_TOK/2)];
__device__ __align__(16) unsigned g_VTl[(size_t)NKV * HD * (T_TOK/2)];
__device__ __align__(16) __half   g_h16[(size_t)T_TOK * HID];
__device__ __align__(16) __half   g_wqkv16[(size_t)HID * QKV_W];
__device__ __align__(16) __half   g_wo16[(size_t)OUT_W * HID];
__device__ __align__(16) __half   g_attn16[(size_t)T_TOK * OUT_W];
__device__ __align__(16) float2   g_rope[(size_t)T_TOK * 64];   // (cos,sin) per (t,i)
__device__ float g_invfreq_pi[HD/2];

// ---------------------------------------------------------------------------
// helpers
// ---------------------------------------------------------------------------
__device__ __forceinline__ unsigned packh2(float x, float y) {
    __half2 h = __floats2half2_rn(x, y);
    return *(unsigned*)&h;
}

__device__ __forceinline__ void split2(float x, float y, unsigned& hi, unsigned& lo) {
    __half hx = __float2half_rn(x);
    __half hy = __float2half_rn(y);
    float rx = x - __half2float(hx);
    float ry = y - __half2float(hy);
    hi = (unsigned)__half_as_ushort(hx) | ((unsigned)__half_as_ushort(hy) << 16);
    lo = (unsigned)__half_as_ushort(__float2half_rn(rx)) |
         ((unsigned)__half_as_ushort(__float2half_rn(ry)) << 16);
}

__device__ __forceinline__ void mma16(float c[4], unsigned a0, unsigned a1,
                                      unsigned a2, unsigned a3,
                                      unsigned b0, unsigned b1) {
    asm volatile(
        "mma.sync.aligned.m16n8k16.row.col.f32.f16.f16.f32 "
        "{%0,%1,%2,%3}, {%4,%5,%6,%7}, {%8,%9}, {%0,%1,%2,%3};\n"
        : "+f"(c[0]), "+f"(c[1]), "+f"(c[2]), "+f"(c[3])
        : "r"(a0), "r"(a1), "r"(a2), "r"(a3), "r"(b0), "r"(b1));
}

__device__ __forceinline__ unsigned smem_u32(const void* p) {
    return (unsigned)__cvta_generic_to_shared(p);
}

__device__ __forceinline__ void ldsm_x4(unsigned& r0, unsigned& r1,
                                        unsigned& r2, unsigned& r3,
                                        unsigned addr) {
    asm volatile("ldmatrix.sync.aligned.m8n8.x4.shared.b16 {%0,%1,%2,%3}, [%4];\n"
                 : "=r"(r0), "=r"(r1), "=r"(r2), "=r"(r3) : "r"(addr));
}

__device__ __forceinline__ void ldsm_x4_t(unsigned& r0, unsigned& r1,
                                          unsigned& r2, unsigned& r3,
                                          unsigned addr) {
    asm volatile("ldmatrix.sync.aligned.m8n8.x4.trans.shared.b16 {%0,%1,%2,%3}, [%4];\n"
                 : "=r"(r0), "=r"(r1), "=r"(r2), "=r"(r3) : "r"(addr));
}

#define CP16(dst, src) \
    asm volatile("cp.async.cg.shared.global [%0], [%1], 16;\n" \
                 :: "r"(dst), "l"(src))
#define CP16A(dst, src) \
    asm volatile("cp.async.ca.shared.global [%0], [%1], 16;\n" \
                 :: "r"(dst), "l"(src))
#define CPCOMMIT() asm volatile("cp.async.commit_group;\n")
#define CPWAIT0()  asm volatile("cp.async.wait_group 0;\n")

// ---------------------------------------------------------------------------
// small kernels
// ---------------------------------------------------------------------------
__global__ void init_invfreq_kernel() {
    int i = threadIdx.x;
    double inv = pow(1.0e6, -((double)(2 * i)) / 128.0);
    g_invfreq_pi[i] = (float)(inv / 3.14159265358979323846);
}

// RoPE trig table: one (cos,sin) per (token, freq) — removes the 40x MUFU
// redundancy that prep_qk had.
__global__ void rope_table_kernel(const int* __restrict__ positions) {
    int t = blockIdx.x;
    int i = threadIdx.x;   // 0..63
    float pos = (float)positions[t];
    float f = pos * g_invfreq_pi[i];
    g_rope[t * 64 + i] = make_float2(cospif(f), sinpif(f));
}

__global__ void conv_f16_kernel(const float4* __restrict__ src,
                                uint2* __restrict__ dst, int n4) {
    int i = blockIdx.x * blockDim.x + threadIdx.x;
    if (i < n4) {
        float4 v = src[i];
        dst[i] = make_uint2(packh2(v.x, v.y), packh2(v.z, v.w));
    }
}

// RoPE + scale + hi/lo split for Q and K heads -> global half2 planes
__global__ void prep_qk_kernel(const float* __restrict__ qkv) {
    int t = blockIdx.x;
    int h = blockIdx.y;
    int i = threadIdx.x;
    float2 cs = g_rope[t * 64 + i];
    float c = cs.x;
    float s = cs.y;
    const float* base = qkv + (size_t)t * QKV_W + h * HD;
    float x1 = base[2 * i];
    float x2 = base[2 * i + 1];
    float o1 = x1 * c - x2 * s;
    float o2 = x2 * c + x1 * s;
    unsigned hi, lo;
    if (h < NH) {
        o1 *= SM_SCALE;
        o2 *= SM_SCALE;
        split2(o1, o2, hi, lo);
        g_Qh[(size_t)t * 2048 + h * 64 + i] = hi;
        g_Ql[(size_t)t * 2048 + h * 64 + i] = lo;
    } else {
        int kh = h - NH;
        split2(o1, o2, hi, lo);
        g_Kh[(size_t)t * 512 + kh * 64 + i] = hi;
        g_Kl[(size_t)t * 512 + kh * 64 + i] = lo;
    }
}

// V split + transpose: VT[hk][d][token-pair word]
__global__ __launch_bounds__(256) void prep_v_kernel(const float* __restrict__ qkv) {
    __shared__ float Vs[64 * 133];
    int bt = blockIdx.x;
    int hk = blockIdx.y;
    int tid = threadIdx.x;
    const float* vb = qkv + (size_t)bt * 64 * QKV_W + (NH + NKV) * HD + hk * HD;
#pragma unroll
    for (int it = 0; it < 8; it++) {
        int idx = tid + it * 256;
        int r = idx >> 5;
        int c4 = (idx & 31) * 4;
        float4 v = *(const float4*)(vb + (size_t)r * QKV_W + c4);
        Vs[r * 133 + c4 + 0] = v.x;
        Vs[r * 133 + c4 + 1] = v.y;
        Vs[r * 133 + c4 + 2] = v.z;
        Vs[r * 133 + c4 + 3] = v.w;
    }
    __syncthreads();
#pragma unroll
    for (int it = 0; it < 16; it++) {
        int d = it * 8 + (tid >> 5);
        int jw = tid & 31;
        float v0 = Vs[(2 * jw) * 133 + d];
        float v1 = Vs[(2 * jw + 1) * 133 + d];
        unsigned hi, lo;
        split2(v0, v1, hi, lo);
        size_t w = (size_t)(hk * 128 + d) * (T_TOK / 2) + bt * 32 + jw;
        g_VTh[w] = hi;
        g_VTl[w] = lo;
    }
}

// ---------------------------------------------------------------------------
// fp16 HGEMM (round-5 proven config): C[M,N] f32 = A[M,K]h @ B[K,N]h.
// 128x128 tile, BK=32, 8 warps (2x4 -> 64x32 per warp), cp.async double buf.
// ---------------------------------------------------------------------------
#define GA_STR 40
#define GB_STR 136

__global__ __launch_bounds__(256) void hgemm(const __half* __restrict__ A,
                                             const __half* __restrict__ B,
                                             float* __restrict__ C,
                                             int M, int N, int K) {
    __shared__ __half As[2][128 * GA_STR];
    __shared__ __half Bs[2][32 * GB_STR];

    int tid = threadIdx.x;
    int warp = tid >> 5;
    int lane = tid & 31;
    int wm = warp >> 2;
    int wn = warp & 3;
    int m_warp = wm * 64;
    int n_warp = wn * 32;
    int gid = lane >> 2;
    int tig = lane & 3;
    int lrow = (lane & 7) + ((lane >> 3) & 1) * 8;
    int lcol8 = (lane >> 4) * 8;

    const __half* Ab = A + (size_t)blockIdx.y * 128 * K;
    const __half* Bb = B + (size_t)blockIdx.x * 128;
    float* Cb = C + (size_t)blockIdx.y * 128 * N + (size_t)blockIdx.x * 128;

    float acc[4][4][4];
#pragma unroll
    for (int mt = 0; mt < 4; mt++)
#pragma unroll
        for (int ng = 0; ng < 4; ng++)
#pragma unroll
            for (int q = 0; q < 4; q++) acc[mt][ng][q] = 0.f;

    auto stage = [&](int buf, int k0) {
#pragma unroll
        for (int it = 0; it < 2; it++) {
            int idx = tid + it * 256;          // 0..511
            int r = idx >> 2;                  // 0..127
            int c8 = (idx & 3) * 8;            // 0..24
            CP16(smem_u32(&As[buf][r * GA_STR + c8]),
                 Ab + (size_t)r * K + k0 + c8);
        }
#pragma unroll
        for (int it = 0; it < 2; it++) {
            int idx = tid + it * 256;
            int r = idx >> 4;                  // 0..31
            int c8 = (idx & 15) * 8;           // 0..120
            CP16(smem_u32(&Bs[buf][r * GB_STR + c8]),
                 Bb + (size_t)(k0 + r) * N + c8);
        }
    };

    stage(0, 0);
    CPCOMMIT();

    int cur = 0;
    for (int k0 = 0; k0 < K; k0 += 32) {
        CPWAIT0();
        __syncthreads();
        if (k0 + 32 < K) {
            stage(cur ^ 1, k0 + 32);
            CPCOMMIT();
        }

        const __half* Ac = As[cur];
        const __half* Bc = Bs[cur];
#pragma unroll
        for (int ks = 0; ks < 32; ks += 16) {
            unsigned bf[2][4];
#pragma unroll
            for (int nt = 0; nt < 2; nt++) {
                ldsm_x4_t(bf[nt][0], bf[nt][1], bf[nt][2], bf[nt][3],
                          smem_u32(Bc + (ks + lrow) * GB_STR + n_warp + nt * 16 + lcol8));
            }
#pragma unroll
            for (int mt = 0; mt < 4; mt++) {
                unsigned a0, a1, a2, a3;
                ldsm_x4(a0, a1, a2, a3,
                        smem_u32(Ac + (m_warp + mt * 16 + lrow) * GA_STR + ks + lcol8));
                mma16(acc[mt][0], a0, a1, a2, a3, bf[0][0], bf[0][1]);
                mma16(acc[mt][1], a0, a1, a2, a3, bf[0][2], bf[0][3]);
                mma16(acc[mt][2], a0, a1, a2, a3, bf[1][0], bf[1][1]);
                mma16(acc[mt][3], a0, a1, a2, a3, bf[1][2], bf[1][3]);
            }
        }
        cur ^= 1;
    }

#pragma unroll
    for (int mt = 0; mt < 4; mt++) {
#pragma unroll
        for (int ng = 0; ng < 4; ng++) {
            int row0 = m_warp + mt * 16 + gid;
            int col  = n_warp + ng * 8 + tig * 2;
            *(float2*)(Cb + (size_t)row0 * N + col) =
                make_float2(acc[mt][ng][0], acc[mt][ng][1]);
            *(float2*)(Cb + (size_t)(row0 + 8) * N + col) =
                make_float2(acc[mt][ng][2], acc[mt][ng][3]);
        }
    }
}

// ---------------------------------------------------------------------------
// Flash attention: precomputed split planes, cp.async staging, ldmatrix.
// (unchanged from round 5 passing build)
// ---------------------------------------------------------------------------
#define QK_STR 68
#define VT_STR 36
#define PH_STR 36

#define QH0_OFF 0
#define QH1_OFF (128*QK_STR)
#define KH0_OFF (QH1_OFF + 128*QK_STR)
#define KH1_OFF (KH0_OFF + 64*QK_STR)
#define VT0_OFF (KH1_OFF + 64*QK_STR)
#define VT1_OFF (VT0_OFF + 128*VT_STR)
#define PH0_OFF (VT1_OFF + 128*VT_STR)
#define PH1_OFF (PH0_OFF + 128*PH_STR)
#define FLASH_SMEM_WORDS (PH1_OFF + 128*PH_STR)
#define FLASH_SMEM_BYTES (FLASH_SMEM_WORDS * 4)

__global__ __launch_bounds__(256) void flash16_kernel(__half* __restrict__ out16) {
    extern __shared__ unsigned sw[];
    unsigned* QH0 = sw + QH0_OFF;
    unsigned* QH1 = sw + QH1_OFF;
    unsigned* KH0 = sw + KH0_OFF;
    unsigned* KH1 = sw + KH1_OFF;
    unsigned* VT0 = sw + VT0_OFF;
    unsigned* VT1 = sw + VT1_OFF;
    unsigned* PH0 = sw + PH0_OFF;
    unsigned* PH1 = sw + PH1_OFF;

    int qb = gridDim.x - 1 - blockIdx.x;
    int hq = blockIdx.y;
    int hk = hq >> 2;
    int tid = threadIdx.x;
    int warp = tid >> 5;
    int lane = tid & 31;
    int gid = lane >> 2;
    int tig = lane & 3;
    int m0 = warp * 16;

    int lrow  = (lane & 7) + ((lane >> 3) & 1) * 8;
    int acol4 = ((lane >> 4) & 1) * 4;
    int krow  = (lane & 7) + ((lane >> 4) & 1) * 8;
    int kcol4 = ((lane >> 3) & 1) * 4;

#pragma unroll
    for (int it = 0; it < 8; it++) {
        int idx = tid + it * 256;
        int r = idx >> 4;
        int c = (idx & 15) * 4;
        const unsigned* s0 = g_Qh + (size_t)(qb * 128 + r) * 2048 + hq * 64 + c;
        const unsigned* s1 = g_Ql + (size_t)(qb * 128 + r) * 2048 + hq * 64 + c;
        CP16A(smem_u32(QH0 + r * QK_STR + c), s0);
        CP16A(smem_u32(QH1 + r * QK_STR + c), s1);
    }

    float mprev0 = -1e30f, mprev1 = -1e30f;
    float lsum0 = 0.f, lsum1 = 0.f;
    float acco[16][4];
#pragma unroll
    for (int dt = 0; dt < 16; dt++)
#pragma unroll
        for (int q = 0; q < 4; q++) acco[dt][q] = 0.f;

    int grow0 = qb * 128 + m0 + gid;
    int grow1 = grow0 + 8;

    int nkt = 2 * qb + 2;
    for (int kt = 0; kt < nkt; kt++) {
        __syncthreads();

#pragma unroll
        for (int it = 0; it < 4; it++) {
            int idx = tid + it * 256;
            int r = idx >> 4;
            int c = (idx & 15) * 4;
            const unsigned* s0 = g_Kh + (size_t)(kt * 64 + r) * 512 + hk * 64 + c;
            const unsigned* s1 = g_Kl + (size_t)(kt * 64 + r) * 512 + hk * 64 + c;
            CP16A(smem_u32(KH0 + r * QK_STR + c), s0);
            CP16A(smem_u32(KH1 + r * QK_STR + c), s1);
        }
#pragma unroll
        for (int it = 0; it < 4; it++) {
            int idx = tid + it * 256;
            int r = idx >> 3;
            int c = (idx & 7) * 4;
            const unsigned* s0 = g_VTh + (size_t)(hk * 128 + r) * (T_TOK/2) + kt * 32 + c;
            const unsigned* s1 = g_VTl + (size_t)(hk * 128 + r) * (T_TOK/2) + kt * 32 + c;
            CP16A(smem_u32(VT0 + r * VT_STR + c), s0);
            CP16A(smem_u32(VT1 + r * VT_STR + c), s1);
        }
        CPCOMMIT();
        CPWAIT0();
        __syncthreads();

        float accs[8][4];
#pragma unroll
        for (int nt = 0; nt < 8; nt++)
#pragma unroll
            for (int q = 0; q < 4; q++) accs[nt][q] = 0.f;

#pragma unroll
        for (int ks = 0; ks < 8; ks++) {
            unsigned ah[4], al[4];
            ldsm_x4(ah[0], ah[1], ah[2], ah[3],
                    smem_u32(QH0 + (m0 + lrow) * QK_STR + ks * 8 + acol4));
            ldsm_x4(al[0], al[1], al[2], al[3],
                    smem_u32(QH1 + (m0 + lrow) * QK_STR + ks * 8 + acol4));
#pragma unroll
            for (int nt2 = 0; nt2 < 4; nt2++) {
                unsigned bh[4], bl[4];
                ldsm_x4(bh[0], bh[1], bh[2], bh[3],
                        smem_u32(KH0 + (nt2 * 16 + krow) * QK_STR + ks * 8 + kcol4));
                ldsm_x4(bl[0], bl[1], bl[2], bl[3],
                        smem_u32(KH1 + (nt2 * 16 + krow) * QK_STR + ks * 8 + kcol4));
                mma16(accs[2*nt2],   ah[0], ah[1], ah[2], ah[3], bh[0], bh[1]);
                mma16(accs[2*nt2],   ah[0], ah[1], ah[2], ah[3], bl[0], bl[1]);
                mma16(accs[2*nt2],   al[0], al[1], al[2], al[3], bh[0], bh[1]);
                mma16(accs[2*nt2+1], ah[0], ah[1], ah[2], ah[3], bh[2], bh[3]);
                mma16(accs[2*nt2+1], ah[0], ah[1], ah[2], ah[3], bl[2], bl[3]);
                mma16(accs[2*nt2+1], al[0], al[1], al[2], al[3], bh[2], bh[3]);
            }
        }

        int colb = kt * 64 + 2 * tig;
        float mx0 = -1e30f, mx1 = -1e30f;
#pragma unroll
        for (int nt = 0; nt < 8; nt++) {
            int c0 = colb + nt * 8;
            int c1 = c0 + 1;
            accs[nt][0] = (c0 <= grow0) ? accs[nt][0] : -1e30f;
            accs[nt][1] = (c1 <= grow0) ? accs[nt][1] : -1e30f;
            accs[nt][2] = (c0 <= grow1) ? accs[nt][2] : -1e30f;
            accs[nt][3] = (c1 <= grow1) ? accs[nt][3] : -1e30f;
            mx0 = fmaxf(mx0, fmaxf(accs[nt][0], accs[nt][1]));
            mx1 = fmaxf(mx1, fmaxf(accs[nt][2], accs[nt][3]));
        }
        mx0 = fmaxf(mx0, __shfl_xor_sync(0xffffffffu, mx0, 1));
        mx0 = fmaxf(mx0, __shfl_xor_sync(0xffffffffu, mx0, 2));
        mx1 = fmaxf(mx1, __shfl_xor_sync(0xffffffffu, mx1, 1));
        mx1 = fmaxf(mx1, __shfl_xor_sync(0xffffffffu, mx1, 2));

        float mn0 = fmaxf(mprev0, mx0);
        float mn1 = fmaxf(mprev1, mx1);
        float corr0 = __expf(mprev0 - mn0);
        float corr1 = __expf(mprev1 - mn1);
        mprev0 = mn0;
        mprev1 = mn1;

        float sum0 = 0.f, sum1 = 0.f;
#pragma unroll
        for (int nt = 0; nt < 8; nt++) {
            accs[nt][0] = __expf(accs[nt][0] - mn0);
            accs[nt][1] = __expf(accs[nt][1] - mn0);
            accs[nt][2] = __expf(accs[nt][2] - mn1);
            accs[nt][3] = __expf(accs[nt][3] - mn1);
            sum0 += accs[nt][0] + accs[nt][1];
            sum1 += accs[nt][2] + accs[nt][3];
        }
        sum0 += __shfl_xor_sync(0xffffffffu, sum0, 1);
        sum0 += __shfl_xor_sync(0xffffffffu, sum0, 2);
        sum1 += __shfl_xor_sync(0xffffffffu, sum1, 1);
        sum1 += __shfl_xor_sync(0xffffffffu, sum1, 2);
        lsum0 = lsum0 * corr0 + sum0;
        lsum1 = lsum1 * corr1 + sum1;

#pragma unroll
        for (int dt = 0; dt < 16; dt++) {
            acco[dt][0] *= corr0;
            acco[dt][1] *= corr0;
            acco[dt][2] *= corr1;
            acco[dt][3] *= corr1;
        }

#pragma unroll
        for (int nt = 0; nt < 8; nt++) {
            unsigned hi0, lo0, hi1, lo1;
            split2(accs[nt][0], accs[nt][1], hi0, lo0);
            split2(accs[nt][2], accs[nt][3], hi1, lo1);
            int w0 = (m0 + gid) * PH_STR + nt * 4 + tig;
            int w1 = (m0 + gid + 8) * PH_STR + nt * 4 + tig;
            PH0[w0] = hi0;
            PH1[w0] = lo0;
            PH0[w1] = hi1;
            PH1[w1] = lo1;
        }
        __syncwarp();

#pragma unroll
        for (int ks = 0; ks < 4; ks++) {
            unsigned ah[4], al[4];
            ldsm_x4(ah[0], ah[1], ah[2], ah[3],
                    smem_u32(PH0 + (m0 + lrow) * PH_STR + ks * 8 + acol4));
            ldsm_x4(al[0], al[1], al[2], al[3],
                    smem_u32(PH1 + (m0 + lrow) * PH_STR + ks * 8 + acol4));
#pragma unroll
            for (int dt2 = 0; dt2 < 8; dt2++) {
                unsigned vh[4], vl[4];
                ldsm_x4(vh[0], vh[1], vh[2], vh[3],
                        smem_u32(VT0 + (dt2 * 16 + krow) * VT_STR + ks * 8 + kcol4));
                ldsm_x4(vl[0], vl[1], vl[2], vl[3],
                        smem_u32(VT1 + (dt2 * 16 + krow) * VT_STR + ks * 8 + kcol4));
                mma16(acco[2*dt2],   ah[0], ah[1], ah[2], ah[3], vh[0], vh[1]);
                mma16(acco[2*dt2],   ah[0], ah[1], ah[2], ah[3], vl[0], vl[1]);
                mma16(acco[2*dt2],   al[0], al[1], al[2], al[3], vh[0], vh[1]);
                mma16(acco[2*dt2+1], ah[0], ah[1], ah[2], ah[3], vh[2], vh[3]);
                mma16(acco[2*dt2+1], ah[0], ah[1], ah[2], ah[3], vl[2], vl[3]);
                mma16(acco[2*dt2+1], al[0], al[1], al[2], al[3], vh[2], vh[3]);
            }
        }
    }

    float il0 = 1.0f / lsum0;
    float il1 = 1.0f / lsum1;
    __half* o0 = out16 + (size_t)grow0 * OUT_W + hq * HD;
    __half* o1 = out16 + (size_t)grow1 * OUT_W + hq * HD;
#pragma unroll
    for (int dt = 0; dt < 16; dt++) {
        int col = dt * 8 + 2 * tig;
        *(unsigned*)(o0 + col) = packh2(acco[dt][0] * il0, acco[dt][1] * il0);
        *(unsigned*)(o1 + col) = packh2(acco[dt][2] * il1, acco[dt][3] * il1);
    }
}

// ---------------------------------------------------------------------------
// launch
// ---------------------------------------------------------------------------
extern "C" void kernel_launch(void* const* d_in, const int* in_sizes, int n_in,
                              void* d_out, int out_size) {
    (void)in_sizes; (void)n_in; (void)out_size;
    const int*   positions = (const int*)d_in[0];
    const float* hidden    = (const float*)d_in[1];
    const float* Wqkv      = (const float*)d_in[2];
    const float* Wo        = (const float*)d_in[3];
    float*       out       = (float*)d_out;

    void *qkv_p, *h16_p, *wqkv16_p, *wo16_p, *attn16_p;
    cudaGetSymbolAddress(&qkv_p, g_qkv);
    cudaGetSymbolAddress(&h16_p, g_h16);
    cudaGetSymbolAddress(&wqkv16_p, g_wqkv16);
    cudaGetSymbolAddress(&wo16_p, g_wo16);
    cudaGetSymbolAddress(&attn16_p, g_attn16);
    float*  qkv    = (float*)qkv_p;
    __half* h16    = (__half*)h16_p;
    __half* wqkv16 = (__half*)wqkv16_p;
    __half* wo16   = (__half*)wo16_p;
    __half* attn16 = (__half*)attn16_p;

    cudaFuncSetAttribute(flash16_kernel,
                         cudaFuncAttributeMaxDynamicSharedMemorySize,
                         FLASH_SMEM_BYTES);

    init_invfreq_kernel<<<1, 64>>>();
    rope_table_kernel<<<T_TOK, 64>>>(positions);

    // fp32 -> fp16 conversions
    {
        int n4 = T_TOK * HID / 4;
        conv_f16_kernel<<<(n4 + 255) / 256, 256>>>((const float4*)hidden,
                                                   (uint2*)h16, n4);
        n4 = HID * QKV_W / 4;
        conv_f16_kernel<<<(n4 + 255) / 256, 256>>>((const float4*)Wqkv,
                                                   (uint2*)wqkv16, n4);
        n4 = OUT_W * HID / 4;
        conv_f16_kernel<<<(n4 + 255) / 256, 256>>>((const float4*)Wo,
                                                   (uint2*)wo16, n4);
    }

    // qkv = hidden @ Wqkv
    hgemm<<<dim3(QKV_W / 128, T_TOK / 128), 256>>>(h16, wqkv16, qkv,
                                                   T_TOK, QKV_W, HID);

    // RoPE + split planes; V split + transpose
    prep_qk_kernel<<<dim3(T_TOK, NH + NKV), 64>>>(qkv);
    prep_v_kernel<<<dim3(T_TOK / 64, NKV), 256>>>(qkv);

    // flash attention
    flash16_kernel<<<dim3(T_TOK / 128, NH), 256, FLASH_SMEM_BYTES>>>(attn16);

    // out = attn @ Wo
    hgemm<<<dim3(HID / 128, T_TOK / 128), 256>>>(attn16, wo16, out,
                                                 T_TOK, HID, HID);
}

// round 10
// speedup vs baseline: 1.0432x; 1.0118x over previous
#include <cuda_runtime.h>
#include <cuda_fp16.h>
#include <cuda_bf16.h>
#include <math.h>
#include <cstdint>

// Problem constants
#define T_TOK 2048
#define HID   4096
#define NH    32
#define NKV   8
#define HD    128
#define QKV_W ((NH + 2*NKV) * HD)   // 6144
#define OUT_W (NH * HD)             // 4096
#define SM_SCALE 0.08838834764831843f  // 1/sqrt(128)

// ---------------------------------------------------------------------------
// Scratch (allocation-free -> device globals), all 16B-aligned for cp.async
// ---------------------------------------------------------------------------
__device__ __align__(16) float    g_qkv[(size_t)T_TOK * QKV_W];   // V region only used
__device__ __align__(16) unsigned g_Qh[(size_t)T_TOK * 2048];
__device__ __align__(16) unsigned g_Ql[(size_t)T_TOK * 2048];
__device__ __align__(16) unsigned g_Kh[(size_t)T_TOK * 512];
__device__ __align__(16) unsigned g_Kl[(size_t)T_TOK * 512];
__device__ __align__(16) unsigned g_VTh[(size_t)NKV * HD * (T_TOK/2)];
__device__ __align__(16) unsigned g_VTl[(size_t)NKV * HD * (T_TOK/2)];
__device__ __align__(16) __half   g_h16[(size_t)T_TOK * HID];
__device__ __align__(16) __half   g_wqkv16[(size_t)HID * QKV_W];
__device__ __align__(16) __half   g_wo16[(size_t)OUT_W * HID];
__device__ __align__(16) __half   g_attn16[(size_t)T_TOK * OUT_W];
__device__ __align__(16) float2   g_rope[(size_t)T_TOK * 64];   // (cos,sin) per (t,i)
__device__ float g_invfreq_pi[HD/2];

// ---------------------------------------------------------------------------
// helpers
// ---------------------------------------------------------------------------
__device__ __forceinline__ unsigned packh2(float x, float y) {
    __half2 h = __floats2half2_rn(x, y);
    return *(unsigned*)&h;
}

__device__ __forceinline__ void split2(float x, float y, unsigned& hi, unsigned& lo) {
    __half hx = __float2half_rn(x);
    __half hy = __float2half_rn(y);
    float rx = x - __half2float(hx);
    float ry = y - __half2float(hy);
    hi = (unsigned)__half_as_ushort(hx) | ((unsigned)__half_as_ushort(hy) << 16);
    lo = (unsigned)__half_as_ushort(__float2half_rn(rx)) |
         ((unsigned)__half_as_ushort(__float2half_rn(ry)) << 16);
}

__device__ __forceinline__ void mma16(float c[4], unsigned a0, unsigned a1,
                                      unsigned a2, unsigned a3,
                                      unsigned b0, unsigned b1) {
    asm volatile(
        "mma.sync.aligned.m16n8k16.row.col.f32.f16.f16.f32 "
        "{%0,%1,%2,%3}, {%4,%5,%6,%7}, {%8,%9}, {%0,%1,%2,%3};\n"
        : "+f"(c[0]), "+f"(c[1]), "+f"(c[2]), "+f"(c[3])
        : "r"(a0), "r"(a1), "r"(a2), "r"(a3), "r"(b0), "r"(b1));
}

__device__ __forceinline__ unsigned smem_u32(const void* p) {
    return (unsigned)__cvta_generic_to_shared(p);
}

__device__ __forceinline__ void ldsm_x4(unsigned& r0, unsigned& r1,
                                        unsigned& r2, unsigned& r3,
                                        unsigned addr) {
    asm volatile("ldmatrix.sync.aligned.m8n8.x4.shared.b16 {%0,%1,%2,%3}, [%4];\n"
                 : "=r"(r0), "=r"(r1), "=r"(r2), "=r"(r3) : "r"(addr));
}

__device__ __forceinline__ void ldsm_x4_t(unsigned& r0, unsigned& r1,
                                          unsigned& r2, unsigned& r3,
                                          unsigned addr) {
    asm volatile("ldmatrix.sync.aligned.m8n8.x4.trans.shared.b16 {%0,%1,%2,%3}, [%4];\n"
                 : "=r"(r0), "=r"(r1), "=r"(r2), "=r"(r3) : "r"(addr));
}

#define CP16(dst, src) \
    asm volatile("cp.async.cg.shared.global [%0], [%1], 16;\n" \
                 :: "r"(dst), "l"(src))
#define CP16A(dst, src) \
    asm volatile("cp.async.ca.shared.global [%0], [%1], 16;\n" \
                 :: "r"(dst), "l"(src))
#define CPCOMMIT() asm volatile("cp.async.commit_group;\n")
#define CPWAIT0()  asm volatile("cp.async.wait_group 0;\n")

// ---------------------------------------------------------------------------
// small kernels
// ---------------------------------------------------------------------------
__global__ void init_invfreq_kernel() {
    int i = threadIdx.x;
    double inv = pow(1.0e6, -((double)(2 * i)) / 128.0);
    g_invfreq_pi[i] = (float)(inv / 3.14159265358979323846);
}

// RoPE trig table: one (cos,sin) per (token, freq)
__global__ void rope_table_kernel(const int* __restrict__ positions) {
    int t = blockIdx.x;
    int i = threadIdx.x;   // 0..63
    float pos = (float)positions[t];
    float f = pos * g_invfreq_pi[i];
    g_rope[t * 64 + i] = make_float2(cospif(f), sinpif(f));
}

__global__ void conv_f16_kernel(const float4* __restrict__ src,
                                uint2* __restrict__ dst, int n4) {
    int i = blockIdx.x * blockDim.x + threadIdx.x;
    if (i < n4) {
        float4 v = src[i];
        dst[i] = make_uint2(packh2(v.x, v.y), packh2(v.z, v.w));
    }
}

// V split + transpose: VT[hk][d][token-pair word]
__global__ __launch_bounds__(256) void prep_v_kernel(const float* __restrict__ qkv) {
    __shared__ float Vs[64 * 133];
    int bt = blockIdx.x;
    int hk = blockIdx.y;
    int tid = threadIdx.x;
    const float* vb = qkv + (size_t)bt * 64 * QKV_W + (NH + NKV) * HD + hk * HD;
#pragma unroll
    for (int it = 0; it < 8; it++) {
        int idx = tid + it * 256;
        int r = idx >> 5;
        int c4 = (idx & 31) * 4;
        float4 v = *(const float4*)(vb + (size_t)r * QKV_W + c4);
        Vs[r * 133 + c4 + 0] = v.x;
        Vs[r * 133 + c4 + 1] = v.y;
        Vs[r * 133 + c4 + 2] = v.z;
        Vs[r * 133 + c4 + 3] = v.w;
    }
    __syncthreads();
#pragma unroll
    for (int it = 0; it < 16; it++) {
        int d = it * 8 + (tid >> 5);
        int jw = tid & 31;
        float v0 = Vs[(2 * jw) * 133 + d];
        float v1 = Vs[(2 * jw + 1) * 133 + d];
        unsigned hi, lo;
        split2(v0, v1, hi, lo);
        size_t w = (size_t)(hk * 128 + d) * (T_TOK / 2) + bt * 32 + jw;
        g_VTh[w] = hi;
        g_VTl[w] = lo;
    }
}

// ---------------------------------------------------------------------------
// fp16 HGEMM (round-5 proven config) with optional fused QKV epilogue.
// C[M,N] f32 = A[M,K]h @ B[K,N]h.
// 128x128 tile, BK=32, 8 warps (2x4 -> 64x32 per warp), cp.async double buf.
// mode 0: plain fp32 C store.
// mode 1 (QKV): block col region is uniform (Q: bn<32, K: 32..39, V: >=40).
//   Q/K: apply RoPE (from g_rope) + scale + hi/lo split, write planes directly.
//   V:   plain fp32 store into g_qkv (prep_v reads it).
// ---------------------------------------------------------------------------
#define GA_STR 40
#define GB_STR 136

__global__ __launch_bounds__(256) void hgemm(const __half* __restrict__ A,
                                             const __half* __restrict__ B,
                                             float* __restrict__ C,
                                             int M, int N, int K, int mode) {
    __shared__ __half As[2][128 * GA_STR];
    __shared__ __half Bs[2][32 * GB_STR];

    int tid = threadIdx.x;
    int warp = tid >> 5;
    int lane = tid & 31;
    int wm = warp >> 2;
    int wn = warp & 3;
    int m_warp = wm * 64;
    int n_warp = wn * 32;
    int gid = lane >> 2;
    int tig = lane & 3;
    int lrow = (lane & 7) + ((lane >> 3) & 1) * 8;
    int lcol8 = (lane >> 4) * 8;

    const __half* Ab = A + (size_t)blockIdx.y * 128 * K;
    const __half* Bb = B + (size_t)blockIdx.x * 128;
    float* Cb = C + (size_t)blockIdx.y * 128 * N + (size_t)blockIdx.x * 128;

    float acc[4][4][4];
#pragma unroll
    for (int mt = 0; mt < 4; mt++)
#pragma unroll
        for (int ng = 0; ng < 4; ng++)
#pragma unroll
            for (int q = 0; q < 4; q++) acc[mt][ng][q] = 0.f;

    auto stage = [&](int buf, int k0) {
#pragma unroll
        for (int it = 0; it < 2; it++) {
            int idx = tid + it * 256;          // 0..511
            int r = idx >> 2;                  // 0..127
            int c8 = (idx & 3) * 8;            // 0..24
            CP16(smem_u32(&As[buf][r * GA_STR + c8]),
                 Ab + (size_t)r * K + k0 + c8);
        }
#pragma unroll
        for (int it = 0; it < 2; it++) {
            int idx = tid + it * 256;
            int r = idx >> 4;                  // 0..31
            int c8 = (idx & 15) * 8;           // 0..120
            CP16(smem_u32(&Bs[buf][r * GB_STR + c8]),
                 Bb + (size_t)(k0 + r) * N + c8);
        }
    };

    stage(0, 0);
    CPCOMMIT();

    int cur = 0;
    for (int k0 = 0; k0 < K; k0 += 32) {
        CPWAIT0();
        __syncthreads();
        if (k0 + 32 < K) {
            stage(cur ^ 1, k0 + 32);
            CPCOMMIT();
        }

        const __half* Ac = As[cur];
        const __half* Bc = Bs[cur];
#pragma unroll
        for (int ks = 0; ks < 32; ks += 16) {
            unsigned bf[2][4];
#pragma unroll
            for (int nt = 0; nt < 2; nt++) {
                ldsm_x4_t(bf[nt][0], bf[nt][1], bf[nt][2], bf[nt][3],
                          smem_u32(Bc + (ks + lrow) * GB_STR + n_warp + nt * 16 + lcol8));
            }
#pragma unroll
            for (int mt = 0; mt < 4; mt++) {
                unsigned a0, a1, a2, a3;
                ldsm_x4(a0, a1, a2, a3,
                        smem_u32(Ac + (m_warp + mt * 16 + lrow) * GA_STR + ks + lcol8));
                mma16(acc[mt][0], a0, a1, a2, a3, bf[0][0], bf[0][1]);
                mma16(acc[mt][1], a0, a1, a2, a3, bf[0][2], bf[0][3]);
                mma16(acc[mt][2], a0, a1, a2, a3, bf[1][0], bf[1][1]);
                mma16(acc[mt][3], a0, a1, a2, a3, bf[1][2], bf[1][3]);
            }
        }
        cur ^= 1;
    }

    // ---- epilogue ----
    int col0 = blockIdx.x * 128;           // global column of this block
    bool fused = (mode == 1) && (col0 < (NH + NKV) * HD);
    if (!fused) {
        // plain fp32 store (mode 0, or V region of QKV)
#pragma unroll
        for (int mt = 0; mt < 4; mt++) {
#pragma unroll
            for (int ng = 0; ng < 4; ng++) {
                int row0 = m_warp + mt * 16 + gid;
                int col  = n_warp + ng * 8 + tig * 2;
                *(float2*)(Cb + (size_t)row0 * N + col) =
                    make_float2(acc[mt][ng][0], acc[mt][ng][1]);
                *(float2*)(Cb + (size_t)(row0 + 8) * N + col) =
                    make_float2(acc[mt][ng][2], acc[mt][ng][3]);
            }
        }
    } else {
        bool isQ = (col0 < NH * HD);
        int tbase = blockIdx.y * 128;
#pragma unroll
        for (int mt = 0; mt < 4; mt++) {
#pragma unroll
            for (int ng = 0; ng < 4; ng++) {
                int t0 = tbase + m_warp + mt * 16 + gid;
                int t1 = t0 + 8;
                int col = col0 + n_warp + ng * 8 + tig * 2;   // even
                int i = (col & 127) >> 1;                     // freq index
                float2 cs0 = g_rope[t0 * 64 + i];
                float2 cs1 = g_rope[t1 * 64 + i];
                float x1a = acc[mt][ng][0], x2a = acc[mt][ng][1];
                float x1b = acc[mt][ng][2], x2b = acc[mt][ng][3];
                float o1a = x1a * cs0.x - x2a * cs0.y;
                float o2a = x2a * cs0.x + x1a * cs0.y;
                float o1b = x1b * cs1.x - x2b * cs1.y;
                float o2b = x2b * cs1.x + x1b * cs1.y;
                unsigned hiA, loA, hiB, loB;
                if (isQ) {
                    o1a *= SM_SCALE; o2a *= SM_SCALE;
                    o1b *= SM_SCALE; o2b *= SM_SCALE;
                    split2(o1a, o2a, hiA, loA);
                    split2(o1b, o2b, hiB, loB);
                    int w = col >> 1;          // 0..2047
                    g_Qh[(size_t)t0 * 2048 + w] = hiA;
                    g_Ql[(size_t)t0 * 2048 + w] = loA;
                    g_Qh[(size_t)t1 * 2048 + w] = hiB;
                    g_Ql[(size_t)t1 * 2048 + w] = loB;
                } else {
                    split2(o1a, o2a, hiA, loA);
                    split2(o1b, o2b, hiB, loB);
                    int w = (col - NH * HD) >> 1;   // 0..511
                    g_Kh[(size_t)t0 * 512 + w] = hiA;
                    g_Kl[(size_t)t0 * 512 + w] = loA;
                    g_Kh[(size_t)t1 * 512 + w] = hiB;
                    g_Kl[(size_t)t1 * 512 + w] = loB;
                }
            }
        }
    }
}

// ---------------------------------------------------------------------------
// Flash attention: precomputed split planes, cp.async staging, ldmatrix.
// (unchanged from round 5 passing build)
// ---------------------------------------------------------------------------
#define QK_STR 68
#define VT_STR 36
#define PH_STR 36

#define QH0_OFF 0
#define QH1_OFF (128*QK_STR)
#define KH0_OFF (QH1_OFF + 128*QK_STR)
#define KH1_OFF (KH0_OFF + 64*QK_STR)
#define VT0_OFF (KH1_OFF + 64*QK_STR)
#define VT1_OFF (VT0_OFF + 128*VT_STR)
#define PH0_OFF (VT1_OFF + 128*VT_STR)
#define PH1_OFF (PH0_OFF + 128*PH_STR)
#define FLASH_SMEM_WORDS (PH1_OFF + 128*PH_STR)
#define FLASH_SMEM_BYTES (FLASH_SMEM_WORDS * 4)

__global__ __launch_bounds__(256) void flash16_kernel(__half* __restrict__ out16) {
    extern __shared__ unsigned sw[];
    unsigned* QH0 = sw + QH0_OFF;
    unsigned* QH1 = sw + QH1_OFF;
    unsigned* KH0 = sw + KH0_OFF;
    unsigned* KH1 = sw + KH1_OFF;
    unsigned* VT0 = sw + VT0_OFF;
    unsigned* VT1 = sw + VT1_OFF;
    unsigned* PH0 = sw + PH0_OFF;
    unsigned* PH1 = sw + PH1_OFF;

    int qb = gridDim.x - 1 - blockIdx.x;
    int hq = blockIdx.y;
    int hk = hq >> 2;
    int tid = threadIdx.x;
    int warp = tid >> 5;
    int lane = tid & 31;
    int gid = lane >> 2;
    int tig = lane & 3;
    int m0 = warp * 16;

    int lrow  = (lane & 7) + ((lane >> 3) & 1) * 8;
    int acol4 = ((lane >> 4) & 1) * 4;
    int krow  = (lane & 7) + ((lane >> 4) & 1) * 8;
    int kcol4 = ((lane >> 3) & 1) * 4;

#pragma unroll
    for (int it = 0; it < 8; it++) {
        int idx = tid + it * 256;
        int r = idx >> 4;
        int c = (idx & 15) * 4;
        const unsigned* s0 = g_Qh + (size_t)(qb * 128 + r) * 2048 + hq * 64 + c;
        const unsigned* s1 = g_Ql + (size_t)(qb * 128 + r) * 2048 + hq * 64 + c;
        CP16A(smem_u32(QH0 + r * QK_STR + c), s0);
        CP16A(smem_u32(QH1 + r * QK_STR + c), s1);
    }

    float mprev0 = -1e30f, mprev1 = -1e30f;
    float lsum0 = 0.f, lsum1 = 0.f;
    float acco[16][4];
#pragma unroll
    for (int dt = 0; dt < 16; dt++)
#pragma unroll
        for (int q = 0; q < 4; q++) acco[dt][q] = 0.f;

    int grow0 = qb * 128 + m0 + gid;
    int grow1 = grow0 + 8;

    int nkt = 2 * qb + 2;
    for (int kt = 0; kt < nkt; kt++) {
        __syncthreads();

#pragma unroll
        for (int it = 0; it < 4; it++) {
            int idx = tid + it * 256;
            int r = idx >> 4;
            int c = (idx & 15) * 4;
            const unsigned* s0 = g_Kh + (size_t)(kt * 64 + r) * 512 + hk * 64 + c;
            const unsigned* s1 = g_Kl + (size_t)(kt * 64 + r) * 512 + hk * 64 + c;
            CP16A(smem_u32(KH0 + r * QK_STR + c), s0);
            CP16A(smem_u32(KH1 + r * QK_STR + c), s1);
        }
#pragma unroll
        for (int it = 0; it < 4; it++) {
            int idx = tid + it * 256;
            int r = idx >> 3;
            int c = (idx & 7) * 4;
            const unsigned* s0 = g_VTh + (size_t)(hk * 128 + r) * (T_TOK/2) + kt * 32 + c;
            const unsigned* s1 = g_VTl + (size_t)(hk * 128 + r) * (T_TOK/2) + kt * 32 + c;
            CP16A(smem_u32(VT0 + r * VT_STR + c), s0);
            CP16A(smem_u32(VT1 + r * VT_STR + c), s1);
        }
        CPCOMMIT();
        CPWAIT0();
        __syncthreads();

        float accs[8][4];
#pragma unroll
        for (int nt = 0; nt < 8; nt++)
#pragma unroll
            for (int q = 0; q < 4; q++) accs[nt][q] = 0.f;

#pragma unroll
        for (int ks = 0; ks < 8; ks++) {
            unsigned ah[4], al[4];
            ldsm_x4(ah[0], ah[1], ah[2], ah[3],
                    smem_u32(QH0 + (m0 + lrow) * QK_STR + ks * 8 + acol4));
            ldsm_x4(al[0], al[1], al[2], al[3],
                    smem_u32(QH1 + (m0 + lrow) * QK_STR + ks * 8 + acol4));
#pragma unroll
            for (int nt2 = 0; nt2 < 4; nt2++) {
                unsigned bh[4], bl[4];
                ldsm_x4(bh[0], bh[1], bh[2], bh[3],
                        smem_u32(KH0 + (nt2 * 16 + krow) * QK_STR + ks * 8 + kcol4));
                ldsm_x4(bl[0], bl[1], bl[2], bl[3],
                        smem_u32(KH1 + (nt2 * 16 + krow) * QK_STR + ks * 8 + kcol4));
                mma16(accs[2*nt2],   ah[0], ah[1], ah[2], ah[3], bh[0], bh[1]);
                mma16(accs[2*nt2],   ah[0], ah[1], ah[2], ah[3], bl[0], bl[1]);
                mma16(accs[2*nt2],   al[0], al[1], al[2], al[3], bh[0], bh[1]);
                mma16(accs[2*nt2+1], ah[0], ah[1], ah[2], ah[3], bh[2], bh[3]);
                mma16(accs[2*nt2+1], ah[0], ah[1], ah[2], ah[3], bl[2], bl[3]);
                mma16(accs[2*nt2+1], al[0], al[1], al[2], al[3], bh[2], bh[3]);
            }
        }

        int colb = kt * 64 + 2 * tig;
        float mx0 = -1e30f, mx1 = -1e30f;
#pragma unroll
        for (int nt = 0; nt < 8; nt++) {
            int c0 = colb + nt * 8;
            int c1 = c0 + 1;
            accs[nt][0] = (c0 <= grow0) ? accs[nt][0] : -1e30f;
            accs[nt][1] = (c1 <= grow0) ? accs[nt][1] : -1e30f;
            accs[nt][2] = (c0 <= grow1) ? accs[nt][2] : -1e30f;
            accs[nt][3] = (c1 <= grow1) ? accs[nt][3] : -1e30f;
            mx0 = fmaxf(mx0, fmaxf(accs[nt][0], accs[nt][1]));
            mx1 = fmaxf(mx1, fmaxf(accs[nt][2], accs[nt][3]));
        }
        mx0 = fmaxf(mx0, __shfl_xor_sync(0xffffffffu, mx0, 1));
        mx0 = fmaxf(mx0, __shfl_xor_sync(0xffffffffu, mx0, 2));
        mx1 = fmaxf(mx1, __shfl_xor_sync(0xffffffffu, mx1, 1));
        mx1 = fmaxf(mx1, __shfl_xor_sync(0xffffffffu, mx1, 2));

        float mn0 = fmaxf(mprev0, mx0);
        float mn1 = fmaxf(mprev1, mx1);
        float corr0 = __expf(mprev0 - mn0);
        float corr1 = __expf(mprev1 - mn1);
        mprev0 = mn0;
        mprev1 = mn1;

        float sum0 = 0.f, sum1 = 0.f;
#pragma unroll
        for (int nt = 0; nt < 8; nt++) {
            accs[nt][0] = __expf(accs[nt][0] - mn0);
            accs[nt][1] = __expf(accs[nt][1] - mn0);
            accs[nt][2] = __expf(accs[nt][2] - mn1);
            accs[nt][3] = __expf(accs[nt][3] - mn1);
            sum0 += accs[nt][0] + accs[nt][1];
            sum1 += accs[nt][2] + accs[nt][3];
        }
        sum0 += __shfl_xor_sync(0xffffffffu, sum0, 1);
        sum0 += __shfl_xor_sync(0xffffffffu, sum0, 2);
        sum1 += __shfl_xor_sync(0xffffffffu, sum1, 1);
        sum1 += __shfl_xor_sync(0xffffffffu, sum1, 2);
        lsum0 = lsum0 * corr0 + sum0;
        lsum1 = lsum1 * corr1 + sum1;

#pragma unroll
        for (int dt = 0; dt < 16; dt++) {
            acco[dt][0] *= corr0;
            acco[dt][1] *= corr0;
            acco[dt][2] *= corr1;
            acco[dt][3] *= corr1;
        }

#pragma unroll
        for (int nt = 0; nt < 8; nt++) {
            unsigned hi0, lo0, hi1, lo1;
            split2(accs[nt][0], accs[nt][1], hi0, lo0);
            split2(accs[nt][2], accs[nt][3], hi1, lo1);
            int w0 = (m0 + gid) * PH_STR + nt * 4 + tig;
            int w1 = (m0 + gid + 8) * PH_STR + nt * 4 + tig;
            PH0[w0] = hi0;
            PH1[w0] = lo0;
            PH0[w1] = hi1;
            PH1[w1] = lo1;
        }
        __syncwarp();

#pragma unroll
        for (int ks = 0; ks < 4; ks++) {
            unsigned ah[4], al[4];
            ldsm_x4(ah[0], ah[1], ah[2], ah[3],
                    smem_u32(PH0 + (m0 + lrow) * PH_STR + ks * 8 + acol4));
            ldsm_x4(al[0], al[1], al[2], al[3],
                    smem_u32(PH1 + (m0 + lrow) * PH_STR + ks * 8 + acol4));
#pragma unroll
            for (int dt2 = 0; dt2 < 8; dt2++) {
                unsigned vh[4], vl[4];
                ldsm_x4(vh[0], vh[1], vh[2], vh[3],
                        smem_u32(VT0 + (dt2 * 16 + krow) * VT_STR + ks * 8 + kcol4));
                ldsm_x4(vl[0], vl[1], vl[2], vl[3],
                        smem_u32(VT1 + (dt2 * 16 + krow) * VT_STR + ks * 8 + kcol4));
                mma16(acco[2*dt2],   ah[0], ah[1], ah[2], ah[3], vh[0], vh[1]);
                mma16(acco[2*dt2],   ah[0], ah[1], ah[2], ah[3], vl[0], vl[1]);
                mma16(acco[2*dt2],   al[0], al[1], al[2], al[3], vh[0], vh[1]);
                mma16(acco[2*dt2+1], ah[0], ah[1], ah[2], ah[3], vh[2], vh[3]);
                mma16(acco[2*dt2+1], ah[0], ah[1], ah[2], ah[3], vl[2], vl[3]);
                mma16(acco[2*dt2+1], al[0], al[1], al[2], al[3], vh[2], vh[3]);
            }
        }
    }

    float il0 = 1.0f / lsum0;
    float il1 = 1.0f / lsum1;
    __half* o0 = out16 + (size_t)grow0 * OUT_W + hq * HD;
    __half* o1 = out16 + (size_t)grow1 * OUT_W + hq * HD;
#pragma unroll
    for (int dt = 0; dt < 16; dt++) {
        int col = dt * 8 + 2 * tig;
        *(unsigned*)(o0 + col) = packh2(acco[dt][0] * il0, acco[dt][1] * il0);
        *(unsigned*)(o1 + col) = packh2(acco[dt][2] * il1, acco[dt][3] * il1);
    }
}

// ---------------------------------------------------------------------------
// launch
// ---------------------------------------------------------------------------
extern "C" void kernel_launch(void* const* d_in, const int* in_sizes, int n_in,
                              void* d_out, int out_size) {
    (void)in_sizes; (void)n_in; (void)out_size;
    const int*   positions = (const int*)d_in[0];
    const float* hidden    = (const float*)d_in[1];
    const float* Wqkv      = (const float*)d_in[2];
    const float* Wo        = (const float*)d_in[3];
    float*       out       = (float*)d_out;

    void *qkv_p, *h16_p, *wqkv16_p, *wo16_p, *attn16_p;
    cudaGetSymbolAddress(&qkv_p, g_qkv);
    cudaGetSymbolAddress(&h16_p, g_h16);
    cudaGetSymbolAddress(&wqkv16_p, g_wqkv16);
    cudaGetSymbolAddress(&wo16_p, g_wo16);
    cudaGetSymbolAddress(&attn16_p, g_attn16);
    float*  qkv    = (float*)qkv_p;
    __half* h16    = (__half*)h16_p;
    __half* wqkv16 = (__half*)wqkv16_p;
    __half* wo16   = (__half*)wo16_p;
    __half* attn16 = (__half*)attn16_p;

    cudaFuncSetAttribute(flash16_kernel,
                         cudaFuncAttributeMaxDynamicSharedMemorySize,
                         FLASH_SMEM_BYTES);

    init_invfreq_kernel<<<1, 64>>>();
    rope_table_kernel<<<T_TOK, 64>>>(positions);

    // fp32 -> fp16 conversions
    {
        int n4 = T_TOK * HID / 4;
        conv_f16_kernel<<<(n4 + 255) / 256, 256>>>((const float4*)hidden,
                                                   (uint2*)h16, n4);
        n4 = HID * QKV_W / 4;
        conv_f16_kernel<<<(n4 + 255) / 256, 256>>>((const float4*)Wqkv,
                                                   (uint2*)wqkv16, n4);
        n4 = OUT_W * HID / 4;
        conv_f16_kernel<<<(n4 + 255) / 256, 256>>>((const float4*)Wo,
                                                   (uint2*)wo16, n4);
    }

    // qkv = hidden @ Wqkv — fused RoPE+split epilogue for Q/K, fp32 V
    hgemm<<<dim3(QKV_W / 128, T_TOK / 128), 256>>>(h16, wqkv16, qkv,
                                                   T_TOK, QKV_W, HID, 1);

    // V split + transpose (reads fp32 V region of qkv)
    prep_v_kernel<<<dim3(T_TOK / 64, NKV), 256>>>(qkv);

    // flash attention
    flash16_kernel<<<dim3(T_TOK / 128, NH), 256, FLASH_SMEM_BYTES>>>(attn16);

    // out = attn @ Wo
    hgemm<<<dim3(HID / 128, T_TOK / 128), 256>>>(attn16, wo16, out,
                                                 T_TOK, HID, HID, 0);
}

// round 11
// speedup vs baseline: 1.0663x; 1.0222x over previous
#include <cuda_runtime.h>
#include <cuda_fp16.h>
#include <cuda_bf16.h>
#include <math.h>
#include <cstdint>

// Problem constants
#define T_TOK 2048
#define HID   4096
#define NH    32
#define NKV   8
#define HD    128
#define QKV_W ((NH + 2*NKV) * HD)   // 6144
#define OUT_W (NH * HD)             // 4096
#define SM_SCALE 0.08838834764831843f  // 1/sqrt(128)

// ---------------------------------------------------------------------------
// Scratch (allocation-free -> device globals), all 16B-aligned for cp.async
// ---------------------------------------------------------------------------
__device__ __align__(16) float    g_qkv[(size_t)T_TOK * QKV_W];   // V region only used
__device__ __align__(16) unsigned g_Qh[(size_t)T_TOK * 2048];
__device__ __align__(16) unsigned g_Ql[(size_t)T_TOK * 2048];
__device__ __align__(16) unsigned g_Kh[(size_t)T_TOK * 512];
__device__ __align__(16) unsigned g_Kl[(size_t)T_TOK * 512];
__device__ __align__(16) unsigned g_VTh[(size_t)NKV * HD * (T_TOK/2)];
__device__ __align__(16) unsigned g_VTl[(size_t)NKV * HD * (T_TOK/2)];
__device__ __align__(16) __half   g_h16[(size_t)T_TOK * HID];
__device__ __align__(16) __half   g_wqkv16[(size_t)HID * QKV_W];
__device__ __align__(16) __half   g_wo16[(size_t)OUT_W * HID];
__device__ __align__(16) __half   g_attn16[(size_t)T_TOK * OUT_W];
__device__ __align__(16) float2   g_rope[(size_t)T_TOK * 64];   // (cos,sin) per (t,i)
__device__ float g_invfreq_pi[HD/2];

// ---------------------------------------------------------------------------
// helpers
// ---------------------------------------------------------------------------
__device__ __forceinline__ unsigned packh2(float x, float y) {
    __half2 h = __floats2half2_rn(x, y);
    return *(unsigned*)&h;
}

__device__ __forceinline__ void split2(float x, float y, unsigned& hi, unsigned& lo) {
    __half hx = __float2half_rn(x);
    __half hy = __float2half_rn(y);
    float rx = x - __half2float(hx);
    float ry = y - __half2float(hy);
    hi = (unsigned)__half_as_ushort(hx) | ((unsigned)__half_as_ushort(hy) << 16);
    lo = (unsigned)__half_as_ushort(__float2half_rn(rx)) |
         ((unsigned)__half_as_ushort(__float2half_rn(ry)) << 16);
}

__device__ __forceinline__ void mma16(float c[4], unsigned a0, unsigned a1,
                                      unsigned a2, unsigned a3,
                                      unsigned b0, unsigned b1) {
    asm volatile(
        "mma.sync.aligned.m16n8k16.row.col.f32.f16.f16.f32 "
        "{%0,%1,%2,%3}, {%4,%5,%6,%7}, {%8,%9}, {%0,%1,%2,%3};\n"
        : "+f"(c[0]), "+f"(c[1]), "+f"(c[2]), "+f"(c[3])
        : "r"(a0), "r"(a1), "r"(a2), "r"(a3), "r"(b0), "r"(b1));
}

__device__ __forceinline__ unsigned smem_u32(const void* p) {
    return (unsigned)__cvta_generic_to_shared(p);
}

__device__ __forceinline__ void ldsm_x4(unsigned& r0, unsigned& r1,
                                        unsigned& r2, unsigned& r3,
                                        unsigned addr) {
    asm volatile("ldmatrix.sync.aligned.m8n8.x4.shared.b16 {%0,%1,%2,%3}, [%4];\n"
                 : "=r"(r0), "=r"(r1), "=r"(r2), "=r"(r3) : "r"(addr));
}

__device__ __forceinline__ void ldsm_x4_t(unsigned& r0, unsigned& r1,
                                          unsigned& r2, unsigned& r3,
                                          unsigned addr) {
    asm volatile("ldmatrix.sync.aligned.m8n8.x4.trans.shared.b16 {%0,%1,%2,%3}, [%4];\n"
                 : "=r"(r0), "=r"(r1), "=r"(r2), "=r"(r3) : "r"(addr));
}

#define CP16(dst, src) \
    asm volatile("cp.async.cg.shared.global [%0], [%1], 16;\n" \
                 :: "r"(dst), "l"(src))
#define CP16A(dst, src) \
    asm volatile("cp.async.ca.shared.global [%0], [%1], 16;\n" \
                 :: "r"(dst), "l"(src))
#define CPCOMMIT() asm volatile("cp.async.commit_group;\n")
#define CPWAIT0()  asm volatile("cp.async.wait_group 0;\n")

// ---------------------------------------------------------------------------
// small kernels
// ---------------------------------------------------------------------------
__global__ void init_invfreq_kernel() {
    int i = threadIdx.x;
    double inv = pow(1.0e6, -((double)(2 * i)) / 128.0);
    g_invfreq_pi[i] = (float)(inv / 3.14159265358979323846);
}

// RoPE trig table: one (cos,sin) per (token, freq)
__global__ void rope_table_kernel(const int* __restrict__ positions) {
    int t = blockIdx.x;
    int i = threadIdx.x;   // 0..63
    float pos = (float)positions[t];
    float f = pos * g_invfreq_pi[i];
    g_rope[t * 64 + i] = make_float2(cospif(f), sinpif(f));
}

__global__ void conv_f16_kernel(const float4* __restrict__ src,
                                uint2* __restrict__ dst, int n4) {
    int i = blockIdx.x * blockDim.x + threadIdx.x;
    if (i < n4) {
        float4 v = src[i];
        dst[i] = make_uint2(packh2(v.x, v.y), packh2(v.z, v.w));
    }
}

// V split + transpose: VT[hk][d][token-pair word]
__global__ __launch_bounds__(256) void prep_v_kernel(const float* __restrict__ qkv) {
    __shared__ float Vs[64 * 133];
    int bt = blockIdx.x;
    int hk = blockIdx.y;
    int tid = threadIdx.x;
    const float* vb = qkv + (size_t)bt * 64 * QKV_W + (NH + NKV) * HD + hk * HD;
#pragma unroll
    for (int it = 0; it < 8; it++) {
        int idx = tid + it * 256;
        int r = idx >> 5;
        int c4 = (idx & 31) * 4;
        float4 v = *(const float4*)(vb + (size_t)r * QKV_W + c4);
        Vs[r * 133 + c4 + 0] = v.x;
        Vs[r * 133 + c4 + 1] = v.y;
        Vs[r * 133 + c4 + 2] = v.z;
        Vs[r * 133 + c4 + 3] = v.w;
    }
    __syncthreads();
#pragma unroll
    for (int it = 0; it < 16; it++) {
        int d = it * 8 + (tid >> 5);
        int jw = tid & 31;
        float v0 = Vs[(2 * jw) * 133 + d];
        float v1 = Vs[(2 * jw + 1) * 133 + d];
        unsigned hi, lo;
        split2(v0, v1, hi, lo);
        size_t w = (size_t)(hk * 128 + d) * (T_TOK / 2) + bt * 32 + jw;
        g_VTh[w] = hi;
        g_VTl[w] = lo;
    }
}

// ---------------------------------------------------------------------------
// fp16 HGEMM (round-5 proven config) with fused QKV epilogue (round 10).
// ---------------------------------------------------------------------------
#define GA_STR 40
#define GB_STR 136

__global__ __launch_bounds__(256) void hgemm(const __half* __restrict__ A,
                                             const __half* __restrict__ B,
                                             float* __restrict__ C,
                                             int M, int N, int K, int mode) {
    __shared__ __half As[2][128 * GA_STR];
    __shared__ __half Bs[2][32 * GB_STR];

    int tid = threadIdx.x;
    int warp = tid >> 5;
    int lane = tid & 31;
    int wm = warp >> 2;
    int wn = warp & 3;
    int m_warp = wm * 64;
    int n_warp = wn * 32;
    int gid = lane >> 2;
    int tig = lane & 3;
    int lrow = (lane & 7) + ((lane >> 3) & 1) * 8;
    int lcol8 = (lane >> 4) * 8;

    const __half* Ab = A + (size_t)blockIdx.y * 128 * K;
    const __half* Bb = B + (size_t)blockIdx.x * 128;
    float* Cb = C + (size_t)blockIdx.y * 128 * N + (size_t)blockIdx.x * 128;

    float acc[4][4][4];
#pragma unroll
    for (int mt = 0; mt < 4; mt++)
#pragma unroll
        for (int ng = 0; ng < 4; ng++)
#pragma unroll
            for (int q = 0; q < 4; q++) acc[mt][ng][q] = 0.f;

    auto stage = [&](int buf, int k0) {
#pragma unroll
        for (int it = 0; it < 2; it++) {
            int idx = tid + it * 256;          // 0..511
            int r = idx >> 2;                  // 0..127
            int c8 = (idx & 3) * 8;            // 0..24
            CP16(smem_u32(&As[buf][r * GA_STR + c8]),
                 Ab + (size_t)r * K + k0 + c8);
        }
#pragma unroll
        for (int it = 0; it < 2; it++) {
            int idx = tid + it * 256;
            int r = idx >> 4;                  // 0..31
            int c8 = (idx & 15) * 8;           // 0..120
            CP16(smem_u32(&Bs[buf][r * GB_STR + c8]),
                 Bb + (size_t)(k0 + r) * N + c8);
        }
    };

    stage(0, 0);
    CPCOMMIT();

    int cur = 0;
    for (int k0 = 0; k0 < K; k0 += 32) {
        CPWAIT0();
        __syncthreads();
        if (k0 + 32 < K) {
            stage(cur ^ 1, k0 + 32);
            CPCOMMIT();
        }

        const __half* Ac = As[cur];
        const __half* Bc = Bs[cur];
#pragma unroll
        for (int ks = 0; ks < 32; ks += 16) {
            unsigned bf[2][4];
#pragma unroll
            for (int nt = 0; nt < 2; nt++) {
                ldsm_x4_t(bf[nt][0], bf[nt][1], bf[nt][2], bf[nt][3],
                          smem_u32(Bc + (ks + lrow) * GB_STR + n_warp + nt * 16 + lcol8));
            }
#pragma unroll
            for (int mt = 0; mt < 4; mt++) {
                unsigned a0, a1, a2, a3;
                ldsm_x4(a0, a1, a2, a3,
                        smem_u32(Ac + (m_warp + mt * 16 + lrow) * GA_STR + ks + lcol8));
                mma16(acc[mt][0], a0, a1, a2, a3, bf[0][0], bf[0][1]);
                mma16(acc[mt][1], a0, a1, a2, a3, bf[0][2], bf[0][3]);
                mma16(acc[mt][2], a0, a1, a2, a3, bf[1][0], bf[1][1]);
                mma16(acc[mt][3], a0, a1, a2, a3, bf[1][2], bf[1][3]);
            }
        }
        cur ^= 1;
    }

    // ---- epilogue ----
    int col0 = blockIdx.x * 128;
    bool fused = (mode == 1) && (col0 < (NH + NKV) * HD);
    if (!fused) {
#pragma unroll
        for (int mt = 0; mt < 4; mt++) {
#pragma unroll
            for (int ng = 0; ng < 4; ng++) {
                int row0 = m_warp + mt * 16 + gid;
                int col  = n_warp + ng * 8 + tig * 2;
                *(float2*)(Cb + (size_t)row0 * N + col) =
                    make_float2(acc[mt][ng][0], acc[mt][ng][1]);
                *(float2*)(Cb + (size_t)(row0 + 8) * N + col) =
                    make_float2(acc[mt][ng][2], acc[mt][ng][3]);
            }
        }
    } else {
        bool isQ = (col0 < NH * HD);
        int tbase = blockIdx.y * 128;
#pragma unroll
        for (int mt = 0; mt < 4; mt++) {
#pragma unroll
            for (int ng = 0; ng < 4; ng++) {
                int t0 = tbase + m_warp + mt * 16 + gid;
                int t1 = t0 + 8;
                int col = col0 + n_warp + ng * 8 + tig * 2;   // even
                int i = (col & 127) >> 1;
                float2 cs0 = g_rope[t0 * 64 + i];
                float2 cs1 = g_rope[t1 * 64 + i];
                float x1a = acc[mt][ng][0], x2a = acc[mt][ng][1];
                float x1b = acc[mt][ng][2], x2b = acc[mt][ng][3];
                float o1a = x1a * cs0.x - x2a * cs0.y;
                float o2a = x2a * cs0.x + x1a * cs0.y;
                float o1b = x1b * cs1.x - x2b * cs1.y;
                float o2b = x2b * cs1.x + x1b * cs1.y;
                unsigned hiA, loA, hiB, loB;
                if (isQ) {
                    o1a *= SM_SCALE; o2a *= SM_SCALE;
                    o1b *= SM_SCALE; o2b *= SM_SCALE;
                    split2(o1a, o2a, hiA, loA);
                    split2(o1b, o2b, hiB, loB);
                    int w = col >> 1;
                    g_Qh[(size_t)t0 * 2048 + w] = hiA;
                    g_Ql[(size_t)t0 * 2048 + w] = loA;
                    g_Qh[(size_t)t1 * 2048 + w] = hiB;
                    g_Ql[(size_t)t1 * 2048 + w] = loB;
                } else {
                    split2(o1a, o2a, hiA, loA);
                    split2(o1b, o2b, hiB, loB);
                    int w = (col - NH * HD) >> 1;
                    g_Kh[(size_t)t0 * 512 + w] = hiA;
                    g_Kl[(size_t)t0 * 512 + w] = loA;
                    g_Kh[(size_t)t1 * 512 + w] = hiB;
                    g_Kl[(size_t)t1 * 512 + w] = loB;
                }
            }
        }
    }
}

// ---------------------------------------------------------------------------
// Flash attention v4: BQ=64, 128 threads (4 warps x 16 rows), 2 CTAs/SM.
// P.V A-fragments built in registers (no P smem round-trip).
// smem: QH[2][64][68] + KH[2][64][68] + VT[2][128][36] = 104 KB.
// ---------------------------------------------------------------------------
#define QK_STR 68
#define VT_STR 36

#define QH0_OFF 0
#define QH1_OFF (64*QK_STR)                 // 4352
#define KH0_OFF (QH1_OFF + 64*QK_STR)       // 8704
#define KH1_OFF (KH0_OFF + 64*QK_STR)       // 13056
#define VT0_OFF (KH1_OFF + 64*QK_STR)       // 17408
#define VT1_OFF (VT0_OFF + 128*VT_STR)      // 22016
#define FLASH_SMEM_WORDS (VT1_OFF + 128*VT_STR)   // 26624
#define FLASH_SMEM_BYTES (FLASH_SMEM_WORDS * 4)   // 106496

__global__ __launch_bounds__(128) void flash16_kernel(__half* __restrict__ out16) {
    extern __shared__ unsigned sw[];
    unsigned* QH0 = sw + QH0_OFF;
    unsigned* QH1 = sw + QH1_OFF;
    unsigned* KH0 = sw + KH0_OFF;
    unsigned* KH1 = sw + KH1_OFF;
    unsigned* VT0 = sw + VT0_OFF;
    unsigned* VT1 = sw + VT1_OFF;

    int qb = gridDim.x - 1 - blockIdx.x;   // heavy blocks first
    int hq = blockIdx.y;
    int hk = hq >> 2;
    int tid = threadIdx.x;                 // 0..127
    int warp = tid >> 5;                   // 0..3
    int lane = tid & 31;
    int gid = lane >> 2;
    int tig = lane & 3;
    int m0 = warp * 16;

    int lrow  = (lane & 7) + ((lane >> 3) & 1) * 8;
    int acol4 = ((lane >> 4) & 1) * 4;
    int krow  = (lane & 7) + ((lane >> 4) & 1) * 8;
    int kcol4 = ((lane >> 3) & 1) * 4;

    // ---- stage Q (cp.async, once): 64 rows ----
#pragma unroll
    for (int it = 0; it < 8; it++) {
        int idx = tid + it * 128;          // 0..1023
        int r = idx >> 4;                  // 0..63
        int c = (idx & 15) * 4;
        const unsigned* s0 = g_Qh + (size_t)(qb * 64 + r) * 2048 + hq * 64 + c;
        const unsigned* s1 = g_Ql + (size_t)(qb * 64 + r) * 2048 + hq * 64 + c;
        CP16A(smem_u32(QH0 + r * QK_STR + c), s0);
        CP16A(smem_u32(QH1 + r * QK_STR + c), s1);
    }

    float mprev0 = -1e30f, mprev1 = -1e30f;
    float lsum0 = 0.f, lsum1 = 0.f;
    float acco[16][4];
#pragma unroll
    for (int dt = 0; dt < 16; dt++)
#pragma unroll
        for (int q = 0; q < 4; q++) acco[dt][q] = 0.f;

    int grow0 = qb * 64 + m0 + gid;
    int grow1 = grow0 + 8;

    int nkt = qb + 1;
    for (int kt = 0; kt < nkt; kt++) {
        __syncthreads();

        // ---- stage K + VT (cp.async) ----
#pragma unroll
        for (int it = 0; it < 8; it++) {
            int idx = tid + it * 128;      // 0..1023
            int r = idx >> 4;              // 0..63
            int c = (idx & 15) * 4;
            const unsigned* s0 = g_Kh + (size_t)(kt * 64 + r) * 512 + hk * 64 + c;
            const unsigned* s1 = g_Kl + (size_t)(kt * 64 + r) * 512 + hk * 64 + c;
            CP16A(smem_u32(KH0 + r * QK_STR + c), s0);
            CP16A(smem_u32(KH1 + r * QK_STR + c), s1);
        }
#pragma unroll
        for (int it = 0; it < 8; it++) {
            int idx = tid + it * 128;
            int r = idx >> 3;              // d: 0..127
            int c = (idx & 7) * 4;
            const unsigned* s0 = g_VTh + (size_t)(hk * 128 + r) * (T_TOK/2) + kt * 32 + c;
            const unsigned* s1 = g_VTl + (size_t)(hk * 128 + r) * (T_TOK/2) + kt * 32 + c;
            CP16A(smem_u32(VT0 + r * VT_STR + c), s0);
            CP16A(smem_u32(VT1 + r * VT_STR + c), s1);
        }
        CPCOMMIT();
        CPWAIT0();
        __syncthreads();

        // ---- S = Q K^T (3x fp16 split) via ldmatrix ----
        float accs[8][4];
#pragma unroll
        for (int nt = 0; nt < 8; nt++)
#pragma unroll
            for (int q = 0; q < 4; q++) accs[nt][q] = 0.f;

#pragma unroll
        for (int ks = 0; ks < 8; ks++) {
            unsigned ah[4], al[4];
            ldsm_x4(ah[0], ah[1], ah[2], ah[3],
                    smem_u32(QH0 + (m0 + lrow) * QK_STR + ks * 8 + acol4));
            ldsm_x4(al[0], al[1], al[2], al[3],
                    smem_u32(QH1 + (m0 + lrow) * QK_STR + ks * 8 + acol4));
#pragma unroll
            for (int nt2 = 0; nt2 < 4; nt2++) {
                unsigned bh[4], bl[4];
                ldsm_x4(bh[0], bh[1], bh[2], bh[3],
                        smem_u32(KH0 + (nt2 * 16 + krow) * QK_STR + ks * 8 + kcol4));
                ldsm_x4(bl[0], bl[1], bl[2], bl[3],
                        smem_u32(KH1 + (nt2 * 16 + krow) * QK_STR + ks * 8 + kcol4));
                mma16(accs[2*nt2],   ah[0], ah[1], ah[2], ah[3], bh[0], bh[1]);
                mma16(accs[2*nt2],   ah[0], ah[1], ah[2], ah[3], bl[0], bl[1]);
                mma16(accs[2*nt2],   al[0], al[1], al[2], al[3], bh[0], bh[1]);
                mma16(accs[2*nt2+1], ah[0], ah[1], ah[2], ah[3], bh[2], bh[3]);
                mma16(accs[2*nt2+1], ah[0], ah[1], ah[2], ah[3], bl[2], bl[3]);
                mma16(accs[2*nt2+1], al[0], al[1], al[2], al[3], bh[2], bh[3]);
            }
        }

        // ---- causal mask + online softmax ----
        int colb = kt * 64 + 2 * tig;
        float mx0 = -1e30f, mx1 = -1e30f;
#pragma unroll
        for (int nt = 0; nt < 8; nt++) {
            int c0 = colb + nt * 8;
            int c1 = c0 + 1;
            accs[nt][0] = (c0 <= grow0) ? accs[nt][0] : -1e30f;
            accs[nt][1] = (c1 <= grow0) ? accs[nt][1] : -1e30f;
            accs[nt][2] = (c0 <= grow1) ? accs[nt][2] : -1e30f;
            accs[nt][3] = (c1 <= grow1) ? accs[nt][3] : -1e30f;
            mx0 = fmaxf(mx0, fmaxf(accs[nt][0], accs[nt][1]));
            mx1 = fmaxf(mx1, fmaxf(accs[nt][2], accs[nt][3]));
        }
        mx0 = fmaxf(mx0, __shfl_xor_sync(0xffffffffu, mx0, 1));
        mx0 = fmaxf(mx0, __shfl_xor_sync(0xffffffffu, mx0, 2));
        mx1 = fmaxf(mx1, __shfl_xor_sync(0xffffffffu, mx1, 1));
        mx1 = fmaxf(mx1, __shfl_xor_sync(0xffffffffu, mx1, 2));

        float mn0 = fmaxf(mprev0, mx0);
        float mn1 = fmaxf(mprev1, mx1);
        float corr0 = __expf(mprev0 - mn0);
        float corr1 = __expf(mprev1 - mn1);
        mprev0 = mn0;
        mprev1 = mn1;

        float sum0 = 0.f, sum1 = 0.f;
#pragma unroll
        for (int nt = 0; nt < 8; nt++) {
            accs[nt][0] = __expf(accs[nt][0] - mn0);
            accs[nt][1] = __expf(accs[nt][1] - mn0);
            accs[nt][2] = __expf(accs[nt][2] - mn1);
            accs[nt][3] = __expf(accs[nt][3] - mn1);
            sum0 += accs[nt][0] + accs[nt][1];
            sum1 += accs[nt][2] + accs[nt][3];
        }
        sum0 += __shfl_xor_sync(0xffffffffu, sum0, 1);
        sum0 += __shfl_xor_sync(0xffffffffu, sum0, 2);
        sum1 += __shfl_xor_sync(0xffffffffu, sum1, 1);
        sum1 += __shfl_xor_sync(0xffffffffu, sum1, 2);
        lsum0 = lsum0 * corr0 + sum0;
        lsum1 = lsum1 * corr1 + sum1;

#pragma unroll
        for (int dt = 0; dt < 16; dt++) {
            acco[dt][0] *= corr0;
            acco[dt][1] *= corr0;
            acco[dt][2] *= corr1;
            acco[dt][3] *= corr1;
        }

        // ---- O += P V: A-fragments straight from registers ----
#pragma unroll
        for (int kb = 0; kb < 4; kb++) {
            unsigned ah0, al0, ah1, al1, ah2, al2, ah3, al3;
            split2(accs[2*kb][0],   accs[2*kb][1],   ah0, al0);
            split2(accs[2*kb][2],   accs[2*kb][3],   ah1, al1);
            split2(accs[2*kb+1][0], accs[2*kb+1][1], ah2, al2);
            split2(accs[2*kb+1][2], accs[2*kb+1][3], ah3, al3);
#pragma unroll
            for (int dt2 = 0; dt2 < 8; dt2++) {
                unsigned vh[4], vl[4];
                ldsm_x4(vh[0], vh[1], vh[2], vh[3],
                        smem_u32(VT0 + (dt2 * 16 + krow) * VT_STR + kb * 8 + kcol4));
                ldsm_x4(vl[0], vl[1], vl[2], vl[3],
                        smem_u32(VT1 + (dt2 * 16 + krow) * VT_STR + kb * 8 + kcol4));
                mma16(acco[2*dt2],   ah0, ah1, ah2, ah3, vh[0], vh[1]);
                mma16(acco[2*dt2],   ah0, ah1, ah2, ah3, vl[0], vl[1]);
                mma16(acco[2*dt2],   al0, al1, al2, al3, vh[0], vh[1]);
                mma16(acco[2*dt2+1], ah0, ah1, ah2, ah3, vh[2], vh[3]);
                mma16(acco[2*dt2+1], ah0, ah1, ah2, ah3, vl[2], vl[3]);
                mma16(acco[2*dt2+1], al0, al1, al2, al3, vh[2], vh[3]);
            }
        }
    }

    // ---- epilogue: write attn as fp16 ----
    float il0 = 1.0f / lsum0;
    float il1 = 1.0f / lsum1;
    __half* o0 = out16 + (size_t)grow0 * OUT_W + hq * HD;
    __half* o1 = out16 + (size_t)grow1 * OUT_W + hq * HD;
#pragma unroll
    for (int dt = 0; dt < 16; dt++) {
        int col = dt * 8 + 2 * tig;
        *(unsigned*)(o0 + col) = packh2(acco[dt][0] * il0, acco[dt][1] * il0);
        *(unsigned*)(o1 + col) = packh2(acco[dt][2] * il1, acco[dt][3] * il1);
    }
}

// ---------------------------------------------------------------------------
// launch
// ---------------------------------------------------------------------------
extern "C" void kernel_launch(void* const* d_in, const int* in_sizes, int n_in,
                              void* d_out, int out_size) {
    (void)in_sizes; (void)n_in; (void)out_size;
    const int*   positions = (const int*)d_in[0];
    const float* hidden    = (const float*)d_in[1];
    const float* Wqkv      = (const float*)d_in[2];
    const float* Wo        = (const float*)d_in[3];
    float*       out       = (float*)d_out;

    void *qkv_p, *h16_p, *wqkv16_p, *wo16_p, *attn16_p;
    cudaGetSymbolAddress(&qkv_p, g_qkv);
    cudaGetSymbolAddress(&h16_p, g_h16);
    cudaGetSymbolAddress(&wqkv16_p, g_wqkv16);
    cudaGetSymbolAddress(&wo16_p, g_wo16);
    cudaGetSymbolAddress(&attn16_p, g_attn16);
    float*  qkv    = (float*)qkv_p;
    __half* h16    = (__half*)h16_p;
    __half* wqkv16 = (__half*)wqkv16_p;
    __half* wo16   = (__half*)wo16_p;
    __half* attn16 = (__half*)attn16_p;

    cudaFuncSetAttribute(flash16_kernel,
                         cudaFuncAttributeMaxDynamicSharedMemorySize,
                         FLASH_SMEM_BYTES);

    init_invfreq_kernel<<<1, 64>>>();
    rope_table_kernel<<<T_TOK, 64>>>(positions);

    // fp32 -> fp16 conversions
    {
        int n4 = T_TOK * HID / 4;
        conv_f16_kernel<<<(n4 + 255) / 256, 256>>>((const float4*)hidden,
                                                   (uint2*)h16, n4);
        n4 = HID * QKV_W / 4;
        conv_f16_kernel<<<(n4 + 255) / 256, 256>>>((const float4*)Wqkv,
                                                   (uint2*)wqkv16, n4);
        n4 = OUT_W * HID / 4;
        conv_f16_kernel<<<(n4 + 255) / 256, 256>>>((const float4*)Wo,
                                                   (uint2*)wo16, n4);
    }

    // qkv = hidden @ Wqkv — fused RoPE+split epilogue for Q/K, fp32 V
    hgemm<<<dim3(QKV_W / 128, T_TOK / 128), 256>>>(h16, wqkv16, qkv,
                                                   T_TOK, QKV_W, HID, 1);

    // V split + transpose (reads fp32 V region of qkv)
    prep_v_kernel<<<dim3(T_TOK / 64, NKV), 256>>>(qkv);

    // flash attention (BQ=64, 2 CTAs/SM)
    flash16_kernel<<<dim3(T_TOK / 64, NH), 128, FLASH_SMEM_BYTES>>>(attn16);

    // out = attn @ Wo
    hgemm<<<dim3(HID / 128, T_TOK / 128), 256>>>(attn16, wo16, out,
                                                 T_TOK, HID, HID, 0);
}

// round 13
// speedup vs baseline: 1.1229x; 1.0531x over previous
#include <cuda_runtime.h>
#include <cuda_fp16.h>
#include <cuda_bf16.h>
#include <math.h>
#include <cstdint>

// Problem constants
#define T_TOK 2048
#define HID   4096
#define NH    32
#define NKV   8
#define HD    128
#define QKV_W ((NH + 2*NKV) * HD)   // 6144
#define OUT_W (NH * HD)             // 4096
#define SM_SCALE 0.08838834764831843f  // 1/sqrt(128)

// ---------------------------------------------------------------------------
// Scratch (allocation-free -> device globals), all 16B-aligned for cp.async
// ---------------------------------------------------------------------------
__device__ __align__(16) float    g_qkv[(size_t)T_TOK * QKV_W];   // V region only used
__device__ __align__(16) unsigned g_Qh[(size_t)T_TOK * 2048];
__device__ __align__(16) unsigned g_Ql[(size_t)T_TOK * 2048];
__device__ __align__(16) unsigned g_Kh[(size_t)T_TOK * 512];
__device__ __align__(16) unsigned g_Kl[(size_t)T_TOK * 512];
__device__ __align__(16) unsigned g_VTh[(size_t)NKV * HD * (T_TOK/2)];
__device__ __align__(16) unsigned g_VTl[(size_t)NKV * HD * (T_TOK/2)];
__device__ __align__(16) __half   g_h16[(size_t)T_TOK * HID];
__device__ __align__(16) __half   g_wqkv16[(size_t)HID * QKV_W];
__device__ __align__(16) __half   g_wo16[(size_t)OUT_W * HID];
__device__ __align__(16) __half   g_attn16[(size_t)T_TOK * OUT_W];
__device__ __align__(16) float2   g_rope[(size_t)T_TOK * 64];   // (cos,sin) per (t,i)
__device__ float g_invfreq_pi[HD/2];

// ---------------------------------------------------------------------------
// helpers
// ---------------------------------------------------------------------------
__device__ __forceinline__ unsigned packh2(float x, float y) {
    __half2 h = __floats2half2_rn(x, y);
    return *(unsigned*)&h;
}

__device__ __forceinline__ void split2(float x, float y, unsigned& hi, unsigned& lo) {
    __half hx = __float2half_rn(x);
    __half hy = __float2half_rn(y);
    float rx = x - __half2float(hx);
    float ry = y - __half2float(hy);
    hi = (unsigned)__half_as_ushort(hx) | ((unsigned)__half_as_ushort(hy) << 16);
    lo = (unsigned)__half_as_ushort(__float2half_rn(rx)) |
         ((unsigned)__half_as_ushort(__float2half_rn(ry)) << 16);
}

__device__ __forceinline__ void mma16(float c[4], unsigned a0, unsigned a1,
                                      unsigned a2, unsigned a3,
                                      unsigned b0, unsigned b1) {
    asm volatile(
        "mma.sync.aligned.m16n8k16.row.col.f32.f16.f16.f32 "
        "{%0,%1,%2,%3}, {%4,%5,%6,%7}, {%8,%9}, {%0,%1,%2,%3};\n"
        : "+f"(c[0]), "+f"(c[1]), "+f"(c[2]), "+f"(c[3])
        : "r"(a0), "r"(a1), "r"(a2), "r"(a3), "r"(b0), "r"(b1));
}

__device__ __forceinline__ unsigned smem_u32(const void* p) {
    return (unsigned)__cvta_generic_to_shared(p);
}

__device__ __forceinline__ void ldsm_x4(unsigned& r0, unsigned& r1,
                                        unsigned& r2, unsigned& r3,
                                        unsigned addr) {
    asm volatile("ldmatrix.sync.aligned.m8n8.x4.shared.b16 {%0,%1,%2,%3}, [%4];\n"
                 : "=r"(r0), "=r"(r1), "=r"(r2), "=r"(r3) : "r"(addr));
}

__device__ __forceinline__ void ldsm_x4_t(unsigned& r0, unsigned& r1,
                                          unsigned& r2, unsigned& r3,
                                          unsigned addr) {
    asm volatile("ldmatrix.sync.aligned.m8n8.x4.trans.shared.b16 {%0,%1,%2,%3}, [%4];\n"
                 : "=r"(r0), "=r"(r1), "=r"(r2), "=r"(r3) : "r"(addr));
}

#define CP16(dst, src) \
    asm volatile("cp.async.cg.shared.global [%0], [%1], 16;\n" \
                 :: "r"(dst), "l"(src))
#define CP16A(dst, src) \
    asm volatile("cp.async.ca.shared.global [%0], [%1], 16;\n" \
                 :: "r"(dst), "l"(src))
#define CPCOMMIT() asm volatile("cp.async.commit_group;\n")
#define CPWAIT0()  asm volatile("cp.async.wait_group 0;\n")
#define CPWAIT1()  asm volatile("cp.async.wait_group 1;\n")

// ---------------------------------------------------------------------------
// small kernels
// ---------------------------------------------------------------------------
__global__ void init_invfreq_kernel() {
    int i = threadIdx.x;
    double inv = pow(1.0e6, -((double)(2 * i)) / 128.0);
    g_invfreq_pi[i] = (float)(inv / 3.14159265358979323846);
}

// RoPE trig table: one (cos,sin) per (token, freq)
__global__ void rope_table_kernel(const int* __restrict__ positions) {
    int t = blockIdx.x;
    int i = threadIdx.x;   // 0..63
    float pos = (float)positions[t];
    float f = pos * g_invfreq_pi[i];
    g_rope[t * 64 + i] = make_float2(cospif(f), sinpif(f));
}

__global__ void conv_f16_kernel(const float4* __restrict__ src,
                                uint2* __restrict__ dst, int n4) {
    int i = blockIdx.x * blockDim.x + threadIdx.x;
    if (i < n4) {
        float4 v = src[i];
        dst[i] = make_uint2(packh2(v.x, v.y), packh2(v.z, v.w));
    }
}

// V split + transpose: VT[hk][d][token-pair word]
__global__ __launch_bounds__(256) void prep_v_kernel(const float* __restrict__ qkv) {
    __shared__ float Vs[64 * 133];
    int bt = blockIdx.x;
    int hk = blockIdx.y;
    int tid = threadIdx.x;
    const float* vb = qkv + (size_t)bt * 64 * QKV_W + (NH + NKV) * HD + hk * HD;
#pragma unroll
    for (int it = 0; it < 8; it++) {
        int idx = tid + it * 256;
        int r = idx >> 5;
        int c4 = (idx & 31) * 4;
        float4 v = *(const float4*)(vb + (size_t)r * QKV_W + c4);
        Vs[r * 133 + c4 + 0] = v.x;
        Vs[r * 133 + c4 + 1] = v.y;
        Vs[r * 133 + c4 + 2] = v.z;
        Vs[r * 133 + c4 + 3] = v.w;
    }
    __syncthreads();
#pragma unroll
    for (int it = 0; it < 16; it++) {
        int d = it * 8 + (tid >> 5);
        int jw = tid & 31;
        float v0 = Vs[(2 * jw) * 133 + d];
        float v1 = Vs[(2 * jw + 1) * 133 + d];
        unsigned hi, lo;
        split2(v0, v1, hi, lo);
        size_t w = (size_t)(hk * 128 + d) * (T_TOK / 2) + bt * 32 + jw;
        g_VTh[w] = hi;
        g_VTl[w] = lo;
    }
}

// ---------------------------------------------------------------------------
// fp16 HGEMM: 128x128 tile, BK=32, 8 warps (2x4 -> 64x32 per warp),
// 3-stage cp.async ring (wait_group 1 -> 2 chunks in flight), dynamic smem.
// FUSED=true: QKV epilogue (RoPE+split for Q/K cols, fp32 store for V cols).
// ---------------------------------------------------------------------------
#define GA_STR 40
#define GB_STR 136
#define HG_STAGES 3
#define HG_A_HALVES (128 * GA_STR)                 // 5120 halves = 10240 B
#define HG_B_HALVES (32 * GB_STR)                  // 4352 halves = 8704 B
#define HG_STAGE_HALVES (HG_A_HALVES + HG_B_HALVES)
#define HG_SMEM_BYTES (HG_STAGES * HG_STAGE_HALVES * 2)   // 56832

template <bool FUSED>
__global__ __launch_bounds__(256) void hgemm_t(const __half* __restrict__ A,
                                               const __half* __restrict__ B,
                                               float* __restrict__ C,
                                               int M, int N, int K) {
    extern __shared__ __half hsm[];

    int tid = threadIdx.x;
    int warp = tid >> 5;
    int lane = tid & 31;
    int wm = warp >> 2;
    int wn = warp & 3;
    int m_warp = wm * 64;
    int n_warp = wn * 32;
    int gid = lane >> 2;
    int tig = lane & 3;
    int lrow = (lane & 7) + ((lane >> 3) & 1) * 8;
    int lcol8 = (lane >> 4) * 8;

    const __half* Ab = A + (size_t)blockIdx.y * 128 * K;
    const __half* Bb = B + (size_t)blockIdx.x * 128;
    float* Cb = C + (size_t)blockIdx.y * 128 * N + (size_t)blockIdx.x * 128;

    float acc[4][4][4];
#pragma unroll
    for (int mt = 0; mt < 4; mt++)
#pragma unroll
        for (int ng = 0; ng < 4; ng++)
#pragma unroll
            for (int q = 0; q < 4; q++) acc[mt][ng][q] = 0.f;

    int NC = K / 32;

    // stage chunk i into slot i%3 (no-op past the end), always commit a group
    auto stage_commit = [&](int i) {
        if (i < NC) {
            __half* As = hsm + (i % HG_STAGES) * HG_STAGE_HALVES;
            __half* Bs = As + HG_A_HALVES;
            int k0 = i * 32;
#pragma unroll
            for (int it = 0; it < 2; it++) {
                int idx = tid + it * 256;          // 0..511
                int r = idx >> 2;                  // 0..127
                int c8 = (idx & 3) * 8;            // 0..24
                CP16(smem_u32(As + r * GA_STR + c8),
                     Ab + (size_t)r * K + k0 + c8);
            }
#pragma unroll
            for (int it = 0; it < 2; it++) {
                int idx = tid + it * 256;
                int r = idx >> 4;                  // 0..31
                int c8 = (idx & 15) * 8;           // 0..120
                CP16(smem_u32(Bs + r * GB_STR + c8),
                     Bb + (size_t)(k0 + r) * N + c8);
            }
        }
        CPCOMMIT();
    };

    stage_commit(0);
    stage_commit(1);

    for (int i = 0; i < NC; i++) {
        CPWAIT1();              // group i complete (group i+1 may be in flight)
        __syncthreads();        // all warps done reading slot being refilled
        stage_commit(i + 2);    // refill slot (i+2)%3 == (i-1)%3

        const __half* Ac = hsm + (i % HG_STAGES) * HG_STAGE_HALVES;
        const __half* Bc = Ac + HG_A_HALVES;
#pragma unroll
        for (int ks = 0; ks < 32; ks += 16) {
            unsigned bf[2][4];
#pragma unroll
            for (int nt = 0; nt < 2; nt++) {
                ldsm_x4_t(bf[nt][0], bf[nt][1], bf[nt][2], bf[nt][3],
                          smem_u32(Bc + (ks + lrow) * GB_STR + n_warp + nt * 16 + lcol8));
            }
#pragma unroll
            for (int mt = 0; mt < 4; mt++) {
                unsigned a0, a1, a2, a3;
                ldsm_x4(a0, a1, a2, a3,
                        smem_u32(Ac + (m_warp + mt * 16 + lrow) * GA_STR + ks + lcol8));
                mma16(acc[mt][0], a0, a1, a2, a3, bf[0][0], bf[0][1]);
                mma16(acc[mt][1], a0, a1, a2, a3, bf[0][2], bf[0][3]);
                mma16(acc[mt][2], a0, a1, a2, a3, bf[1][0], bf[1][1]);
                mma16(acc[mt][3], a0, a1, a2, a3, bf[1][2], bf[1][3]);
            }
        }
    }

    // ---- epilogue ----
    int col0 = blockIdx.x * 128;
    bool fused_blk = FUSED && (col0 < (NH + NKV) * HD);
    if (!fused_blk) {
#pragma unroll
        for (int mt = 0; mt < 4; mt++) {
#pragma unroll
            for (int ng = 0; ng < 4; ng++) {
                int row0 = m_warp + mt * 16 + gid;
                int col  = n_warp + ng * 8 + tig * 2;
                *(float2*)(Cb + (size_t)row0 * N + col) =
                    make_float2(acc[mt][ng][0], acc[mt][ng][1]);
                *(float2*)(Cb + (size_t)(row0 + 8) * N + col) =
                    make_float2(acc[mt][ng][2], acc[mt][ng][3]);
            }
        }
    } else {
        bool isQ = (col0 < NH * HD);
        int tbase = blockIdx.y * 128;
#pragma unroll
        for (int mt = 0; mt < 4; mt++) {
#pragma unroll
            for (int ng = 0; ng < 4; ng++) {
                int t0 = tbase + m_warp + mt * 16 + gid;
                int t1 = t0 + 8;
                int col = col0 + n_warp + ng * 8 + tig * 2;   // even
                int i = (col & 127) >> 1;
                float2 cs0 = g_rope[t0 * 64 + i];
                float2 cs1 = g_rope[t1 * 64 + i];
                float x1a = acc[mt][ng][0], x2a = acc[mt][ng][1];
                float x1b = acc[mt][ng][2], x2b = acc[mt][ng][3];
                float o1a = x1a * cs0.x - x2a * cs0.y;
                float o2a = x2a * cs0.x + x1a * cs0.y;
                float o1b = x1b * cs1.x - x2b * cs1.y;
                float o2b = x2b * cs1.x + x1b * cs1.y;
                unsigned hiA, loA, hiB, loB;
                if (isQ) {
                    o1a *= SM_SCALE; o2a *= SM_SCALE;
                    o1b *= SM_SCALE; o2b *= SM_SCALE;
                    split2(o1a, o2a, hiA, loA);
                    split2(o1b, o2b, hiB, loB);
                    int w = col >> 1;
                    g_Qh[(size_t)t0 * 2048 + w] = hiA;
                    g_Ql[(size_t)t0 * 2048 + w] = loA;
                    g_Qh[(size_t)t1 * 2048 + w] = hiB;
                    g_Ql[(size_t)t1 * 2048 + w] = loB;
                } else {
                    split2(o1a, o2a, hiA, loA);
                    split2(o1b, o2b, hiB, loB);
                    int w = (col - NH * HD) >> 1;
                    g_Kh[(size_t)t0 * 512 + w] = hiA;
                    g_Kl[(size_t)t0 * 512 + w] = loA;
                    g_Kh[(size_t)t1 * 512 + w] = hiB;
                    g_Kl[(size_t)t1 * 512 + w] = loB;
                }
            }
        }
    }
}

// ---------------------------------------------------------------------------
// Flash attention v4 (round 11): BQ=64, 128 threads, 2 CTAs/SM,
// P.V A-fragments built in registers.
// ---------------------------------------------------------------------------
#define QK_STR 68
#define VT_STR 36

#define QH0_OFF 0
#define QH1_OFF (64*QK_STR)
#define KH0_OFF (QH1_OFF + 64*QK_STR)
#define KH1_OFF (KH0_OFF + 64*QK_STR)
#define VT0_OFF (KH1_OFF + 64*QK_STR)
#define VT1_OFF (VT0_OFF + 128*VT_STR)
#define FLASH_SMEM_WORDS (VT1_OFF + 128*VT_STR)
#define FLASH_SMEM_BYTES (FLASH_SMEM_WORDS * 4)   // 106496

__global__ __launch_bounds__(128) void flash16_kernel(__half* __restrict__ out16) {
    extern __shared__ unsigned sw[];
    unsigned* QH0 = sw + QH0_OFF;
    unsigned* QH1 = sw + QH1_OFF;
    unsigned* KH0 = sw + KH0_OFF;
    unsigned* KH1 = sw + KH1_OFF;
    unsigned* VT0 = sw + VT0_OFF;
    unsigned* VT1 = sw + VT1_OFF;

    int qb = gridDim.x - 1 - blockIdx.x;
    int hq = blockIdx.y;
    int hk = hq >> 2;
    int tid = threadIdx.x;
    int warp = tid >> 5;
    int lane = tid & 31;
    int gid = lane >> 2;
    int tig = lane & 3;
    int m0 = warp * 16;

    int lrow  = (lane & 7) + ((lane >> 3) & 1) * 8;
    int acol4 = ((lane >> 4) & 1) * 4;
    int krow  = (lane & 7) + ((lane >> 4) & 1) * 8;
    int kcol4 = ((lane >> 3) & 1) * 4;

#pragma unroll
    for (int it = 0; it < 8; it++) {
        int idx = tid + it * 128;
        int r = idx >> 4;
        int c = (idx & 15) * 4;
        const unsigned* s0 = g_Qh + (size_t)(qb * 64 + r) * 2048 + hq * 64 + c;
        const unsigned* s1 = g_Ql + (size_t)(qb * 64 + r) * 2048 + hq * 64 + c;
        CP16A(smem_u32(QH0 + r * QK_STR + c), s0);
        CP16A(smem_u32(QH1 + r * QK_STR + c), s1);
    }

    float mprev0 = -1e30f, mprev1 = -1e30f;
    float lsum0 = 0.f, lsum1 = 0.f;
    float acco[16][4];
#pragma unroll
    for (int dt = 0; dt < 16; dt++)
#pragma unroll
        for (int q = 0; q < 4; q++) acco[dt][q] = 0.f;

    int grow0 = qb * 64 + m0 + gid;
    int grow1 = grow0 + 8;

    int nkt = qb + 1;
    for (int kt = 0; kt < nkt; kt++) {
        __syncthreads();

#pragma unroll
        for (int it = 0; it < 8; it++) {
            int idx = tid + it * 128;
            int r = idx >> 4;
            int c = (idx & 15) * 4;
            const unsigned* s0 = g_Kh + (size_t)(kt * 64 + r) * 512 + hk * 64 + c;
            const unsigned* s1 = g_Kl + (size_t)(kt * 64 + r) * 512 + hk * 64 + c;
            CP16A(smem_u32(KH0 + r * QK_STR + c), s0);
            CP16A(smem_u32(KH1 + r * QK_STR + c), s1);
        }
#pragma unroll
        for (int it = 0; it < 8; it++) {
            int idx = tid + it * 128;
            int r = idx >> 3;
            int c = (idx & 7) * 4;
            const unsigned* s0 = g_VTh + (size_t)(hk * 128 + r) * (T_TOK/2) + kt * 32 + c;
            const unsigned* s1 = g_VTl + (size_t)(hk * 128 + r) * (T_TOK/2) + kt * 32 + c;
            CP16A(smem_u32(VT0 + r * VT_STR + c), s0);
            CP16A(smem_u32(VT1 + r * VT_STR + c), s1);
        }
        CPCOMMIT();
        CPWAIT0();
        __syncthreads();

        float accs[8][4];
#pragma unroll
        for (int nt = 0; nt < 8; nt++)
#pragma unroll
            for (int q = 0; q < 4; q++) accs[nt][q] = 0.f;

#pragma unroll
        for (int ks = 0; ks < 8; ks++) {
            unsigned ah[4], al[4];
            ldsm_x4(ah[0], ah[1], ah[2], ah[3],
                    smem_u32(QH0 + (m0 + lrow) * QK_STR + ks * 8 + acol4));
            ldsm_x4(al[0], al[1], al[2], al[3],
                    smem_u32(QH1 + (m0 + lrow) * QK_STR + ks * 8 + acol4));
#pragma unroll
            for (int nt2 = 0; nt2 < 4; nt2++) {
                unsigned bh[4], bl[4];
                ldsm_x4(bh[0], bh[1], bh[2], bh[3],
                        smem_u32(KH0 + (nt2 * 16 + krow) * QK_STR + ks * 8 + kcol4));
                ldsm_x4(bl[0], bl[1], bl[2], bl[3],
                        smem_u32(KH1 + (nt2 * 16 + krow) * QK_STR + ks * 8 + kcol4));
                mma16(accs[2*nt2],   ah[0], ah[1], ah[2], ah[3], bh[0], bh[1]);
                mma16(accs[2*nt2],   ah[0], ah[1], ah[2], ah[3], bl[0], bl[1]);
                mma16(accs[2*nt2],   al[0], al[1], al[2], al[3], bh[0], bh[1]);
                mma16(accs[2*nt2+1], ah[0], ah[1], ah[2], ah[3], bh[2], bh[3]);
                mma16(accs[2*nt2+1], ah[0], ah[1], ah[2], ah[3], bl[2], bl[3]);
                mma16(accs[2*nt2+1], al[0], al[1], al[2], al[3], bh[2], bh[3]);
            }
        }

        int colb = kt * 64 + 2 * tig;
        float mx0 = -1e30f, mx1 = -1e30f;
#pragma unroll
        for (int nt = 0; nt < 8; nt++) {
            int c0 = colb + nt * 8;
            int c1 = c0 + 1;
            accs[nt][0] = (c0 <= grow0) ? accs[nt][0] : -1e30f;
            accs[nt][1] = (c1 <= grow0) ? accs[nt][1] : -1e30f;
            accs[nt][2] = (c0 <= grow1) ? accs[nt][2] : -1e30f;
            accs[nt][3] = (c1 <= grow1) ? accs[nt][3] : -1e30f;
            mx0 = fmaxf(mx0, fmaxf(accs[nt][0], accs[nt][1]));
            mx1 = fmaxf(mx1, fmaxf(accs[nt][2], accs[nt][3]));
        }
        mx0 = fmaxf(mx0, __shfl_xor_sync(0xffffffffu, mx0, 1));
        mx0 = fmaxf(mx0, __shfl_xor_sync(0xffffffffu, mx0, 2));
        mx1 = fmaxf(mx1, __shfl_xor_sync(0xffffffffu, mx1, 1));
        mx1 = fmaxf(mx1, __shfl_xor_sync(0xffffffffu, mx1, 2));

        float mn0 = fmaxf(mprev0, mx0);
        float mn1 = fmaxf(mprev1, mx1);
        float corr0 = __expf(mprev0 - mn0);
        float corr1 = __expf(mprev1 - mn1);
        mprev0 = mn0;
        mprev1 = mn1;

        float sum0 = 0.f, sum1 = 0.f;
#pragma unroll
        for (int nt = 0; nt < 8; nt++) {
            accs[nt][0] = __expf(accs[nt][0] - mn0);
            accs[nt][1] = __expf(accs[nt][1] - mn0);
            accs[nt][2] = __expf(accs[nt][2] - mn1);
            accs[nt][3] = __expf(accs[nt][3] - mn1);
            sum0 += accs[nt][0] + accs[nt][1];
            sum1 += accs[nt][2] + accs[nt][3];
        }
        sum0 += __shfl_xor_sync(0xffffffffu, sum0, 1);
        sum0 += __shfl_xor_sync(0xffffffffu, sum0, 2);
        sum1 += __shfl_xor_sync(0xffffffffu, sum1, 1);
        sum1 += __shfl_xor_sync(0xffffffffu, sum1, 2);
        lsum0 = lsum0 * corr0 + sum0;
        lsum1 = lsum1 * corr1 + sum1;

#pragma unroll
        for (int dt = 0; dt < 16; dt++) {
            acco[dt][0] *= corr0;
            acco[dt][1] *= corr0;
            acco[dt][2] *= corr1;
            acco[dt][3] *= corr1;
        }

#pragma unroll
        for (int kb = 0; kb < 4; kb++) {
            unsigned ah0, al0, ah1, al1, ah2, al2, ah3, al3;
            split2(accs[2*kb][0],   accs[2*kb][1],   ah0, al0);
            split2(accs[2*kb][2],   accs[2*kb][3],   ah1, al1);
            split2(accs[2*kb+1][0], accs[2*kb+1][1], ah2, al2);
            split2(accs[2*kb+1][2], accs[2*kb+1][3], ah3, al3);
#pragma unroll
            for (int dt2 = 0; dt2 < 8; dt2++) {
                unsigned vh[4], vl[4];
                ldsm_x4(vh[0], vh[1], vh[2], vh[3],
                        smem_u32(VT0 + (dt2 * 16 + krow) * VT_STR + kb * 8 + kcol4));
                ldsm_x4(vl[0], vl[1], vl[2], vl[3],
                        smem_u32(VT1 + (dt2 * 16 + krow) * VT_STR + kb * 8 + kcol4));
                mma16(acco[2*dt2],   ah0, ah1, ah2, ah3, vh[0], vh[1]);
                mma16(acco[2*dt2],   ah0, ah1, ah2, ah3, vl[0], vl[1]);
                mma16(acco[2*dt2],   al0, al1, al2, al3, vh[0], vh[1]);
                mma16(acco[2*dt2+1], ah0, ah1, ah2, ah3, vh[2], vh[3]);
                mma16(acco[2*dt2+1], ah0, ah1, ah2, ah3, vl[2], vl[3]);
                mma16(acco[2*dt2+1], al0, al1, al2, al3, vh[2], vh[3]);
            }
        }
    }

    float il0 = 1.0f / lsum0;
    float il1 = 1.0f / lsum1;
    __half* o0 = out16 + (size_t)grow0 * OUT_W + hq * HD;
    __half* o1 = out16 + (size_t)grow1 * OUT_W + hq * HD;
#pragma unroll
    for (int dt = 0; dt < 16; dt++) {
        int col = dt * 8 + 2 * tig;
        *(unsigned*)(o0 + col) = packh2(acco[dt][0] * il0, acco[dt][1] * il0);
        *(unsigned*)(o1 + col) = packh2(acco[dt][2] * il1, acco[dt][3] * il1);
    }
}

// ---------------------------------------------------------------------------
// launch
// ---------------------------------------------------------------------------
extern "C" void kernel_launch(void* const* d_in, const int* in_sizes, int n_in,
                              void* d_out, int out_size) {
    (void)in_sizes; (void)n_in; (void)out_size;
    const int*   positions = (const int*)d_in[0];
    const float* hidden    = (const float*)d_in[1];
    const float* Wqkv      = (const float*)d_in[2];
    const float* Wo        = (const float*)d_in[3];
    float*       out       = (float*)d_out;

    void *qkv_p, *h16_p, *wqkv16_p, *wo16_p, *attn16_p;
    cudaGetSymbolAddress(&qkv_p, g_qkv);
    cudaGetSymbolAddress(&h16_p, g_h16);
    cudaGetSymbolAddress(&wqkv16_p, g_wqkv16);
    cudaGetSymbolAddress(&wo16_p, g_wo16);
    cudaGetSymbolAddress(&attn16_p, g_attn16);
    float*  qkv    = (float*)qkv_p;
    __half* h16    = (__half*)h16_p;
    __half* wqkv16 = (__half*)wqkv16_p;
    __half* wo16   = (__half*)wo16_p;
    __half* attn16 = (__half*)attn16_p;

    cudaFuncSetAttribute(flash16_kernel,
                         cudaFuncAttributeMaxDynamicSharedMemorySize,
                         FLASH_SMEM_BYTES);
    cudaFuncSetAttribute(hgemm_t<true>,
                         cudaFuncAttributeMaxDynamicSharedMemorySize,
                         HG_SMEM_BYTES);
    cudaFuncSetAttribute(hgemm_t<false>,
                         cudaFuncAttributeMaxDynamicSharedMemorySize,
                         HG_SMEM_BYTES);

    init_invfreq_kernel<<<1, 64>>>();
    rope_table_kernel<<<T_TOK, 64>>>(positions);

    // fp32 -> fp16 conversions
    {
        int n4 = T_TOK * HID / 4;
        conv_f16_kernel<<<(n4 + 255) / 256, 256>>>((const float4*)hidden,
                                                   (uint2*)h16, n4);
        n4 = HID * QKV_W / 4;
        conv_f16_kernel<<<(n4 + 255) / 256, 256>>>((const float4*)Wqkv,
                                                   (uint2*)wqkv16, n4);
        n4 = OUT_W * HID / 4;
        conv_f16_kernel<<<(n4 + 255) / 256, 256>>>((const float4*)Wo,
                                                   (uint2*)wo16, n4);
    }

    // qkv = hidden @ Wqkv — fused RoPE+split epilogue for Q/K, fp32 V
    hgemm_t<true><<<dim3(QKV_W / 128, T_TOK / 128), 256, HG_SMEM_BYTES>>>(
        h16, wqkv16, qkv, T_TOK, QKV_W, HID);

    // V split + transpose (reads fp32 V region of qkv)
    prep_v_kernel<<<dim3(T_TOK / 64, NKV), 256>>>(qkv);

    // flash attention (BQ=64, 2 CTAs/SM)
    flash16_kernel<<<dim3(T_TOK / 64, NH), 128, FLASH_SMEM_BYTES>>>(attn16);

    // out = attn @ Wo
    hgemm_t<false><<<dim3(HID / 128, T_TOK / 128), 256, HG_SMEM_BYTES>>>(
        attn16, wo16, out, T_TOK, HID, HID);
}

// round 15
// speedup vs baseline: 1.1535x; 1.0272x over previous
#include <cuda_runtime.h>
#include <cuda_fp16.h>
#include <cuda_bf16.h>
#include <math.h>
#include <cstdint>

// Problem constants
#define T_TOK 2048
#define HID   4096
#define NH    32
#define NKV   8
#define HD    128
#define QKV_W ((NH + 2*NKV) * HD)   // 6144
#define OUT_W (NH * HD)             // 4096
#define SM_SCALE 0.08838834764831843f  // 1/sqrt(128)

// ---------------------------------------------------------------------------
// Scratch (allocation-free -> device globals), all 16B-aligned for cp.async
// ---------------------------------------------------------------------------
__device__ __align__(16) float    g_qkv[(size_t)T_TOK * QKV_W];   // V region only used
__device__ __align__(16) unsigned g_Qh[(size_t)T_TOK * 2048];
__device__ __align__(16) unsigned g_Ql[(size_t)T_TOK * 2048];
__device__ __align__(16) unsigned g_Kh[(size_t)T_TOK * 512];
__device__ __align__(16) unsigned g_Kl[(size_t)T_TOK * 512];
__device__ __align__(16) unsigned g_VTh[(size_t)NKV * HD * (T_TOK/2)];
__device__ __align__(16) unsigned g_VTl[(size_t)NKV * HD * (T_TOK/2)];
__device__ __align__(16) __half   g_h16[(size_t)T_TOK * HID];
__device__ __align__(16) __half   g_wqkv16[(size_t)HID * QKV_W];
__device__ __align__(16) __half   g_wo16[(size_t)OUT_W * HID];
__device__ __align__(16) __half   g_attn16[(size_t)T_TOK * OUT_W];
__device__ __align__(16) float2   g_rope[(size_t)T_TOK * 64];   // (cos,sin) per (t,i)
__device__ float g_invfreq_pi[HD/2];

// ---------------------------------------------------------------------------
// helpers
// ---------------------------------------------------------------------------
__device__ __forceinline__ unsigned packh2(float x, float y) {
    __half2 h = __floats2half2_rn(x, y);
    return *(unsigned*)&h;
}

__device__ __forceinline__ void split2(float x, float y, unsigned& hi, unsigned& lo) {
    __half hx = __float2half_rn(x);
    __half hy = __float2half_rn(y);
    float rx = x - __half2float(hx);
    float ry = y - __half2float(hy);
    hi = (unsigned)__half_as_ushort(hx) | ((unsigned)__half_as_ushort(hy) << 16);
    lo = (unsigned)__half_as_ushort(__float2half_rn(rx)) |
         ((unsigned)__half_as_ushort(__float2half_rn(ry)) << 16);
}

__device__ __forceinline__ void mma16(float c[4], unsigned a0, unsigned a1,
                                      unsigned a2, unsigned a3,
                                      unsigned b0, unsigned b1) {
    asm volatile(
        "mma.sync.aligned.m16n8k16.row.col.f32.f16.f16.f32 "
        "{%0,%1,%2,%3}, {%4,%5,%6,%7}, {%8,%9}, {%0,%1,%2,%3};\n"
        : "+f"(c[0]), "+f"(c[1]), "+f"(c[2]), "+f"(c[3])
        : "r"(a0), "r"(a1), "r"(a2), "r"(a3), "r"(b0), "r"(b1));
}

__device__ __forceinline__ unsigned smem_u32(const void* p) {
    return (unsigned)__cvta_generic_to_shared(p);
}

__device__ __forceinline__ void ldsm_x4(unsigned& r0, unsigned& r1,
                                        unsigned& r2, unsigned& r3,
                                        unsigned addr) {
    asm volatile("ldmatrix.sync.aligned.m8n8.x4.shared.b16 {%0,%1,%2,%3}, [%4];\n"
                 : "=r"(r0), "=r"(r1), "=r"(r2), "=r"(r3) : "r"(addr));
}

__device__ __forceinline__ void ldsm_x4_t(unsigned& r0, unsigned& r1,
                                          unsigned& r2, unsigned& r3,
                                          unsigned addr) {
    asm volatile("ldmatrix.sync.aligned.m8n8.x4.trans.shared.b16 {%0,%1,%2,%3}, [%4];\n"
                 : "=r"(r0), "=r"(r1), "=r"(r2), "=r"(r3) : "r"(addr));
}

#define CP16(dst, src) \
    asm volatile("cp.async.cg.shared.global [%0], [%1], 16;\n" \
                 :: "r"(dst), "l"(src))
#define CP16A(dst, src) \
    asm volatile("cp.async.ca.shared.global [%0], [%1], 16;\n" \
                 :: "r"(dst), "l"(src))
#define CPCOMMIT() asm volatile("cp.async.commit_group;\n")
#define CPWAIT0()  asm volatile("cp.async.wait_group 0;\n")
#define CPWAIT1()  asm volatile("cp.async.wait_group 1;\n")

// ---------------------------------------------------------------------------
// small kernels
// ---------------------------------------------------------------------------
__global__ void init_invfreq_kernel() {
    int i = threadIdx.x;
    double inv = pow(1.0e6, -((double)(2 * i)) / 128.0);
    g_invfreq_pi[i] = (float)(inv / 3.14159265358979323846);
}

// RoPE trig table: one (cos,sin) per (token, freq)
__global__ void rope_table_kernel(const int* __restrict__ positions) {
    int t = blockIdx.x;
    int i = threadIdx.x;   // 0..63
    float pos = (float)positions[t];
    float f = pos * g_invfreq_pi[i];
    g_rope[t * 64 + i] = make_float2(cospif(f), sinpif(f));
}

__global__ void conv_f16_kernel(const float4* __restrict__ src,
                                uint2* __restrict__ dst, int n4) {
    int i = blockIdx.x * blockDim.x + threadIdx.x;
    if (i < n4) {
        float4 v = src[i];
        dst[i] = make_uint2(packh2(v.x, v.y), packh2(v.z, v.w));
    }
}

// V split + transpose: VT[hk][d][token-pair word]
__global__ __launch_bounds__(256) void prep_v_kernel(const float* __restrict__ qkv) {
    __shared__ float Vs[64 * 133];
    int bt = blockIdx.x;
    int hk = blockIdx.y;
    int tid = threadIdx.x;
    const float* vb = qkv + (size_t)bt * 64 * QKV_W + (NH + NKV) * HD + hk * HD;
#pragma unroll
    for (int it = 0; it < 8; it++) {
        int idx = tid + it * 256;
        int r = idx >> 5;
        int c4 = (idx & 31) * 4;
        float4 v = *(const float4*)(vb + (size_t)r * QKV_W + c4);
        Vs[r * 133 + c4 + 0] = v.x;
        Vs[r * 133 + c4 + 1] = v.y;
        Vs[r * 133 + c4 + 2] = v.z;
        Vs[r * 133 + c4 + 3] = v.w;
    }
    __syncthreads();
#pragma unroll
    for (int it = 0; it < 16; it++) {
        int d = it * 8 + (tid >> 5);
        int jw = tid & 31;
        float v0 = Vs[(2 * jw) * 133 + d];
        float v1 = Vs[(2 * jw + 1) * 133 + d];
        unsigned hi, lo;
        split2(v0, v1, hi, lo);
        size_t w = (size_t)(hk * 128 + d) * (T_TOK / 2) + bt * 32 + jw;
        g_VTh[w] = hi;
        g_VTl[w] = lo;
    }
}

// ---------------------------------------------------------------------------
// fp16 HGEMM: 128x128 tile, BK=64 (half the barrier frequency of BK=32),
// 8 warps (2x4 -> 64x32 per warp), 3-stage cp.async ring (wait_group 1),
// dynamic smem (107.5 KB).
// FUSED=true: QKV epilogue (RoPE+split for Q/K cols, fp32 store for V cols).
// ---------------------------------------------------------------------------
#define GA_STR 72     // halves per A smem row (64+8): 36-word row stride -> conflict-free ldsm
#define GB_STR 136    // halves per B smem row (128+8)
#define HG_STAGES 3
#define HG_A_HALVES (128 * GA_STR)                 // 9216 halves
#define HG_B_HALVES (64 * GB_STR)                  // 8704 halves
#define HG_STAGE_HALVES (HG_A_HALVES + HG_B_HALVES)
#define HG_SMEM_BYTES (HG_STAGES * HG_STAGE_HALVES * 2)   // 107520

template <bool FUSED>
__global__ __launch_bounds__(256) void hgemm_t(const __half* __restrict__ A,
                                               const __half* __restrict__ B,
                                               float* __restrict__ C,
                                               int M, int N, int K) {
    extern __shared__ __half hsm[];

    int tid = threadIdx.x;
    int warp = tid >> 5;
    int lane = tid & 31;
    int wm = warp >> 2;
    int wn = warp & 3;
    int m_warp = wm * 64;
    int n_warp = wn * 32;
    int gid = lane >> 2;
    int tig = lane & 3;
    int lrow = (lane & 7) + ((lane >> 3) & 1) * 8;
    int lcol8 = (lane >> 4) * 8;

    const __half* Ab = A + (size_t)blockIdx.y * 128 * K;
    const __half* Bb = B + (size_t)blockIdx.x * 128;
    float* Cb = C + (size_t)blockIdx.y * 128 * N + (size_t)blockIdx.x * 128;

    float acc[4][4][4];
#pragma unroll
    for (int mt = 0; mt < 4; mt++)
#pragma unroll
        for (int ng = 0; ng < 4; ng++)
#pragma unroll
            for (int q = 0; q < 4; q++) acc[mt][ng][q] = 0.f;

    int NC = K / 64;

    // stage 64-K chunk i into slot i%3 (no-op past the end), always commit
    auto stage_commit = [&](int i) {
        if (i < NC) {
            __half* As = hsm + (i % HG_STAGES) * HG_STAGE_HALVES;
            __half* Bs = As + HG_A_HALVES;
            int k0 = i * 64;
            // A: 128 rows x 64 halves = 1024 cp16
#pragma unroll
            for (int it = 0; it < 4; it++) {
                int idx = tid + it * 256;          // 0..1023
                int r = idx >> 3;                  // 0..127
                int c8 = (idx & 7) * 8;            // 0..56
                CP16(smem_u32(As + r * GA_STR + c8),
                     Ab + (size_t)r * K + k0 + c8);
            }
            // B: 64 rows x 128 halves = 1024 cp16
#pragma unroll
            for (int it = 0; it < 4; it++) {
                int idx = tid + it * 256;
                int r = idx >> 4;                  // 0..63
                int c8 = (idx & 15) * 8;           // 0..120
                CP16(smem_u32(Bs + r * GB_STR + c8),
                     Bb + (size_t)(k0 + r) * N + c8);
            }
        }
        CPCOMMIT();
    };

    stage_commit(0);
    stage_commit(1);

    for (int i = 0; i < NC; i++) {
        CPWAIT1();              // chunk i complete (chunk i+1 may be in flight)
        __syncthreads();        // all warps done reading slot being refilled
        stage_commit(i + 2);    // refill slot (i+2)%3 == (i-1)%3

        const __half* Ac = hsm + (i % HG_STAGES) * HG_STAGE_HALVES;
        const __half* Bc = Ac + HG_A_HALVES;
#pragma unroll
        for (int ks = 0; ks < 64; ks += 16) {
            unsigned bf[2][4];
#pragma unroll
            for (int nt = 0; nt < 2; nt++) {
                ldsm_x4_t(bf[nt][0], bf[nt][1], bf[nt][2], bf[nt][3],
                          smem_u32(Bc + (ks + lrow) * GB_STR + n_warp + nt * 16 + lcol8));
            }
#pragma unroll
            for (int mt = 0; mt < 4; mt++) {
                unsigned a0, a1, a2, a3;
                ldsm_x4(a0, a1, a2, a3,
                        smem_u32(Ac + (m_warp + mt * 16 + lrow) * GA_STR + ks + lcol8));
                mma16(acc[mt][0], a0, a1, a2, a3, bf[0][0], bf[0][1]);
                mma16(acc[mt][1], a0, a1, a2, a3, bf[0][2], bf[0][3]);
                mma16(acc[mt][2], a0, a1, a2, a3, bf[1][0], bf[1][1]);
                mma16(acc[mt][3], a0, a1, a2, a3, bf[1][2], bf[1][3]);
            }
        }
    }

    // ---- epilogue ----
    int col0 = blockIdx.x * 128;
    bool fused_blk = FUSED && (col0 < (NH + NKV) * HD);
    if (!fused_blk) {
#pragma unroll
        for (int mt = 0; mt < 4; mt++) {
#pragma unroll
            for (int ng = 0; ng < 4; ng++) {
                int row0 = m_warp + mt * 16 + gid;
                int col  = n_warp + ng * 8 + tig * 2;
                *(float2*)(Cb + (size_t)row0 * N + col) =
                    make_float2(acc[mt][ng][0], acc[mt][ng][1]);
                *(float2*)(Cb + (size_t)(row0 + 8) * N + col) =
                    make_float2(acc[mt][ng][2], acc[mt][ng][3]);
            }
        }
    } else {
        bool isQ = (col0 < NH * HD);
        int tbase = blockIdx.y * 128;
#pragma unroll
        for (int mt = 0; mt < 4; mt++) {
#pragma unroll
            for (int ng = 0; ng < 4; ng++) {
                int t0 = tbase + m_warp + mt * 16 + gid;
                int t1 = t0 + 8;
                int col = col0 + n_warp + ng * 8 + tig * 2;   // even
                int i = (col & 127) >> 1;
                float2 cs0 = g_rope[t0 * 64 + i];
                float2 cs1 = g_rope[t1 * 64 + i];
                float x1a = acc[mt][ng][0], x2a = acc[mt][ng][1];
                float x1b = acc[mt][ng][2], x2b = acc[mt][ng][3];
                float o1a = x1a * cs0.x - x2a * cs0.y;
                float o2a = x2a * cs0.x + x1a * cs0.y;
                float o1b = x1b * cs1.x - x2b * cs1.y;
                float o2b = x2b * cs1.x + x1b * cs1.y;
                unsigned hiA, loA, hiB, loB;
                if (isQ) {
                    o1a *= SM_SCALE; o2a *= SM_SCALE;
                    o1b *= SM_SCALE; o2b *= SM_SCALE;
                    split2(o1a, o2a, hiA, loA);
                    split2(o1b, o2b, hiB, loB);
                    int w = col >> 1;
                    g_Qh[(size_t)t0 * 2048 + w] = hiA;
                    g_Ql[(size_t)t0 * 2048 + w] = loA;
                    g_Qh[(size_t)t1 * 2048 + w] = hiB;
                    g_Ql[(size_t)t1 * 2048 + w] = loB;
                } else {
                    split2(o1a, o2a, hiA, loA);
                    split2(o1b, o2b, hiB, loB);
                    int w = (col - NH * HD) >> 1;
                    g_Kh[(size_t)t0 * 512 + w] = hiA;
                    g_Kl[(size_t)t0 * 512 + w] = loA;
                    g_Kh[(size_t)t1 * 512 + w] = hiB;
                    g_Kl[(size_t)t1 * 512 + w] = loB;
                }
            }
        }
    }
}

// ---------------------------------------------------------------------------
// Flash attention v4: BQ=64, 128 threads, 2 CTAs/SM,
// P.V A-fragments built in registers.
// ---------------------------------------------------------------------------
#define QK_STR 68
#define VT_STR 36

#define QH0_OFF 0
#define QH1_OFF (64*QK_STR)
#define KH0_OFF (QH1_OFF + 64*QK_STR)
#define KH1_OFF (KH0_OFF + 64*QK_STR)
#define VT0_OFF (KH1_OFF + 64*QK_STR)
#define VT1_OFF (VT0_OFF + 128*VT_STR)
#define FLASH_SMEM_WORDS (VT1_OFF + 128*VT_STR)
#define FLASH_SMEM_BYTES (FLASH_SMEM_WORDS * 4)   // 106496

__global__ __launch_bounds__(128) void flash16_kernel(__half* __restrict__ out16) {
    extern __shared__ unsigned sw[];
    unsigned* QH0 = sw + QH0_OFF;
    unsigned* QH1 = sw + QH1_OFF;
    unsigned* KH0 = sw + KH0_OFF;
    unsigned* KH1 = sw + KH1_OFF;
    unsigned* VT0 = sw + VT0_OFF;
    unsigned* VT1 = sw + VT1_OFF;

    int qb = gridDim.x - 1 - blockIdx.x;
    int hq = blockIdx.y;
    int hk = hq >> 2;
    int tid = threadIdx.x;
    int warp = tid >> 5;
    int lane = tid & 31;
    int gid = lane >> 2;
    int tig = lane & 3;
    int m0 = warp * 16;

    int lrow  = (lane & 7) + ((lane >> 3) & 1) * 8;
    int acol4 = ((lane >> 4) & 1) * 4;
    int krow  = (lane & 7) + ((lane >> 4) & 1) * 8;
    int kcol4 = ((lane >> 3) & 1) * 4;

#pragma unroll
    for (int it = 0; it < 8; it++) {
        int idx = tid + it * 128;
        int r = idx >> 4;
        int c = (idx & 15) * 4;
        const unsigned* s0 = g_Qh + (size_t)(qb * 64 + r) * 2048 + hq * 64 + c;
        const unsigned* s1 = g_Ql + (size_t)(qb * 64 + r) * 2048 + hq * 64 + c;
        CP16A(smem_u32(QH0 + r * QK_STR + c), s0);
        CP16A(smem_u32(QH1 + r * QK_STR + c), s1);
    }

    float mprev0 = -1e30f, mprev1 = -1e30f;
    float lsum0 = 0.f, lsum1 = 0.f;
    float acco[16][4];
#pragma unroll
    for (int dt = 0; dt < 16; dt++)
#pragma unroll
        for (int q = 0; q < 4; q++) acco[dt][q] = 0.f;

    int grow0 = qb * 64 + m0 + gid;
    int grow1 = grow0 + 8;

    int nkt = qb + 1;
    for (int kt = 0; kt < nkt; kt++) {
        __syncthreads();

#pragma unroll
        for (int it = 0; it < 8; it++) {
            int idx = tid + it * 128;
            int r = idx >> 4;
            int c = (idx & 15) * 4;
            const unsigned* s0 = g_Kh + (size_t)(kt * 64 + r) * 512 + hk * 64 + c;
            const unsigned* s1 = g_Kl + (size_t)(kt * 64 + r) * 512 + hk * 64 + c;
            CP16A(smem_u32(KH0 + r * QK_STR + c), s0);
            CP16A(smem_u32(KH1 + r * QK_STR + c), s1);
        }
#pragma unroll
        for (int it = 0; it < 8; it++) {
            int idx = tid + it * 128;
            int r = idx >> 3;
            int c = (idx & 7) * 4;
            const unsigned* s0 = g_VTh + (size_t)(hk * 128 + r) * (T_TOK/2) + kt * 32 + c;
            const unsigned* s1 = g_VTl + (size_t)(hk * 128 + r) * (T_TOK/2) + kt * 32 + c;
            CP16A(smem_u32(VT0 + r * VT_STR + c), s0);
            CP16A(smem_u32(VT1 + r * VT_STR + c), s1);
        }
        CPCOMMIT();
        CPWAIT0();
        __syncthreads();

        float accs[8][4];
#pragma unroll
        for (int nt = 0; nt < 8; nt++)
#pragma unroll
            for (int q = 0; q < 4; q++) accs[nt][q] = 0.f;

#pragma unroll
        for (int ks = 0; ks < 8; ks++) {
            unsigned ah[4], al[4];
            ldsm_x4(ah[0], ah[1], ah[2], ah[3],
                    smem_u32(QH0 + (m0 + lrow) * QK_STR + ks * 8 + acol4));
            ldsm_x4(al[0], al[1], al[2], al[3],
                    smem_u32(QH1 + (m0 + lrow) * QK_STR + ks * 8 + acol4));
#pragma unroll
            for (int nt2 = 0; nt2 < 4; nt2++) {
                unsigned bh[4], bl[4];
                ldsm_x4(bh[0], bh[1], bh[2], bh[3],
                        smem_u32(KH0 + (nt2 * 16 + krow) * QK_STR + ks * 8 + kcol4));
                ldsm_x4(bl[0], bl[1], bl[2], bl[3],
                        smem_u32(KH1 + (nt2 * 16 + krow) * QK_STR + ks * 8 + kcol4));
                mma16(accs[2*nt2],   ah[0], ah[1], ah[2], ah[3], bh[0], bh[1]);
                mma16(accs[2*nt2],   ah[0], ah[1], ah[2], ah[3], bl[0], bl[1]);
                mma16(accs[2*nt2],   al[0], al[1], al[2], al[3], bh[0], bh[1]);
                mma16(accs[2*nt2+1], ah[0], ah[1], ah[2], ah[3], bh[2], bh[3]);
                mma16(accs[2*nt2+1], ah[0], ah[1], ah[2], ah[3], bl[2], bl[3]);
                mma16(accs[2*nt2+1], al[0], al[1], al[2], al[3], bh[2], bh[3]);
            }
        }

        int colb = kt * 64 + 2 * tig;
        float mx0 = -1e30f, mx1 = -1e30f;
#pragma unroll
        for (int nt = 0; nt < 8; nt++) {
            int c0 = colb + nt * 8;
            int c1 = c0 + 1;
            accs[nt][0] = (c0 <= grow0) ? accs[nt][0] : -1e30f;
            accs[nt][1] = (c1 <= grow0) ? accs[nt][1] : -1e30f;
            accs[nt][2] = (c0 <= grow1) ? accs[nt][2] : -1e30f;
            accs[nt][3] = (c1 <= grow1) ? accs[nt][3] : -1e30f;
            mx0 = fmaxf(mx0, fmaxf(accs[nt][0], accs[nt][1]));
            mx1 = fmaxf(mx1, fmaxf(accs[nt][2], accs[nt][3]));
        }
        mx0 = fmaxf(mx0, __shfl_xor_sync(0xffffffffu, mx0, 1));
        mx0 = fmaxf(mx0, __shfl_xor_sync(0xffffffffu, mx0, 2));
        mx1 = fmaxf(mx1, __shfl_xor_sync(0xffffffffu, mx1, 1));
        mx1 = fmaxf(mx1, __shfl_xor_sync(0xffffffffu, mx1, 2));

        float mn0 = fmaxf(mprev0, mx0);
        float mn1 = fmaxf(mprev1, mx1);
        float corr0 = __expf(mprev0 - mn0);
        float corr1 = __expf(mprev1 - mn1);
        mprev0 = mn0;
        mprev1 = mn1;

        float sum0 = 0.f, sum1 = 0.f;
#pragma unroll
        for (int nt = 0; nt < 8; nt++) {
            accs[nt][0] = __expf(accs[nt][0] - mn0);
            accs[nt][1] = __expf(accs[nt][1] - mn0);
            accs[nt][2] = __expf(accs[nt][2] - mn1);
            accs[nt][3] = __expf(accs[nt][3] - mn1);
            sum0 += accs[nt][0] + accs[nt][1];
            sum1 += accs[nt][2] + accs[nt][3];
        }
        sum0 += __shfl_xor_sync(0xffffffffu, sum0, 1);
        sum0 += __shfl_xor_sync(0xffffffffu, sum0, 2);
        sum1 += __shfl_xor_sync(0xffffffffu, sum1, 1);
        sum1 += __shfl_xor_sync(0xffffffffu, sum1, 2);
        lsum0 = lsum0 * corr0 + sum0;
        lsum1 = lsum1 * corr1 + sum1;

#pragma unroll
        for (int dt = 0; dt < 16; dt++) {
            acco[dt][0] *= corr0;
            acco[dt][1] *= corr0;
            acco[dt][2] *= corr1;
            acco[dt][3] *= corr1;
        }

#pragma unroll
        for (int kb = 0; kb < 4; kb++) {
            unsigned ah0, al0, ah1, al1, ah2, al2, ah3, al3;
            split2(accs[2*kb][0],   accs[2*kb][1],   ah0, al0);
            split2(accs[2*kb][2],   accs[2*kb][3],   ah1, al1);
            split2(accs[2*kb+1][0], accs[2*kb+1][1], ah2, al2);
            split2(accs[2*kb+1][2], accs[2*kb+1][3], ah3, al3);
#pragma unroll
            for (int dt2 = 0; dt2 < 8; dt2++) {
                unsigned vh[4], vl[4];
                ldsm_x4(vh[0], vh[1], vh[2], vh[3],
                        smem_u32(VT0 + (dt2 * 16 + krow) * VT_STR + kb * 8 + kcol4));
                ldsm_x4(vl[0], vl[1], vl[2], vl[3],
                        smem_u32(VT1 + (dt2 * 16 + krow) * VT_STR + kb * 8 + kcol4));
                mma16(acco[2*dt2],   ah0, ah1, ah2, ah3, vh[0], vh[1]);
                mma16(acco[2*dt2],   ah0, ah1, ah2, ah3, vl[0], vl[1]);
                mma16(acco[2*dt2],   al0, al1, al2, al3, vh[0], vh[1]);
                mma16(acco[2*dt2+1], ah0, ah1, ah2, ah3, vh[2], vh[3]);
                mma16(acco[2*dt2+1], ah0, ah1, ah2, ah3, vl[2], vl[3]);
                mma16(acco[2*dt2+1], al0, al1, al2, al3, vh[2], vh[3]);
            }
        }
    }

    float il0 = 1.0f / lsum0;
    float il1 = 1.0f / lsum1;
    __half* o0 = out16 + (size_t)grow0 * OUT_W + hq * HD;
    __half* o1 = out16 + (size_t)grow1 * OUT_W + hq * HD;
#pragma unroll
    for (int dt = 0; dt < 16; dt++) {
        int col = dt * 8 + 2 * tig;
        *(unsigned*)(o0 + col) = packh2(acco[dt][0] * il0, acco[dt][1] * il0);
        *(unsigned*)(o1 + col) = packh2(acco[dt][2] * il1, acco[dt][3] * il1);
    }
}

// ---------------------------------------------------------------------------
// launch
// ---------------------------------------------------------------------------
extern "C" void kernel_launch(void* const* d_in, const int* in_sizes, int n_in,
                              void* d_out, int out_size) {
    (void)in_sizes; (void)n_in; (void)out_size;
    const int*   positions = (const int*)d_in[0];
    const float* hidden    = (const float*)d_in[1];
    const float* Wqkv      = (const float*)d_in[2];
    const float* Wo        = (const float*)d_in[3];
    float*       out       = (float*)d_out;

    void *qkv_p, *h16_p, *wqkv16_p, *wo16_p, *attn16_p;
    cudaGetSymbolAddress(&qkv_p, g_qkv);
    cudaGetSymbolAddress(&h16_p, g_h16);
    cudaGetSymbolAddress(&wqkv16_p, g_wqkv16);
    cudaGetSymbolAddress(&wo16_p, g_wo16);
    cudaGetSymbolAddress(&attn16_p, g_attn16);
    float*  qkv    = (float*)qkv_p;
    __half* h16    = (__half*)h16_p;
    __half* wqkv16 = (__half*)wqkv16_p;
    __half* wo16   = (__half*)wo16_p;
    __half* attn16 = (__half*)attn16_p;

    cudaFuncSetAttribute(flash16_kernel,
                         cudaFuncAttributeMaxDynamicSharedMemorySize,
                         FLASH_SMEM_BYTES);
    cudaFuncSetAttribute(hgemm_t<true>,
                         cudaFuncAttributeMaxDynamicSharedMemorySize,
                         HG_SMEM_BYTES);
    cudaFuncSetAttribute(hgemm_t<false>,
                         cudaFuncAttributeMaxDynamicSharedMemorySize,
                         HG_SMEM_BYTES);

    init_invfreq_kernel<<<1, 64>>>();
    rope_table_kernel<<<T_TOK, 64>>>(positions);

    // fp32 -> fp16 conversions
    {
        int n4 = T_TOK * HID / 4;
        conv_f16_kernel<<<(n4 + 255) / 256, 256>>>((const float4*)hidden,
                                                   (uint2*)h16, n4);
        n4 = HID * QKV_W / 4;
        conv_f16_kernel<<<(n4 + 255) / 256, 256>>>((const float4*)Wqkv,
                                                   (uint2*)wqkv16, n4);
        n4 = OUT_W * HID / 4;
        conv_f16_kernel<<<(n4 + 255) / 256, 256>>>((const float4*)Wo,
                                                   (uint2*)wo16, n4);
    }

    // qkv = hidden @ Wqkv — fused RoPE+split epilogue for Q/K, fp32 V
    hgemm_t<true><<<dim3(QKV_W / 128, T_TOK / 128), 256, HG_SMEM_BYTES>>>(
        h16, wqkv16, qkv, T_TOK, QKV_W, HID);

    // V split + transpose (reads fp32 V region of qkv)
    prep_v_kernel<<<dim3(T_TOK / 64, NKV), 256>>>(qkv);

    // flash attention (BQ=64, 2 CTAs/SM)
    flash16_kernel<<<dim3(T_TOK / 64, NH), 128, FLASH_SMEM_BYTES>>>(attn16);

    // out = attn @ Wo
    hgemm_t<false><<<dim3(HID / 128, T_TOK / 128), 256, HG_SMEM_BYTES>>>(
        attn16, wo16, out, T_TOK, HID, HID);
}

// round 16
// speedup vs baseline: 1.2482x; 1.0821x over previous
#include <cuda_runtime.h>
#include <cuda_fp16.h>
#include <cuda_bf16.h>
#include <math.h>
#include <cstdint>

// Problem constants
#define T_TOK 2048
#define HID   4096
#define NH    32
#define NKV   8
#define HD    128
#define QKV_W ((NH + 2*NKV) * HD)   // 6144
#define OUT_W (NH * HD)             // 4096
#define SM_SCALE 0.08838834764831843f  // 1/sqrt(128)

// ---------------------------------------------------------------------------
// Scratch (allocation-free -> device globals), all 16B-aligned for cp.async
// ---------------------------------------------------------------------------
__device__ __align__(16) float    g_qkv[(size_t)T_TOK * QKV_W];   // V region only used
__device__ __align__(16) unsigned g_Qh[(size_t)T_TOK * 2048];
__device__ __align__(16) unsigned g_Ql[(size_t)T_TOK * 2048];
__device__ __align__(16) unsigned g_Kh[(size_t)T_TOK * 512];
__device__ __align__(16) unsigned g_Kl[(size_t)T_TOK * 512];
__device__ __align__(16) unsigned g_VTh[(size_t)NKV * HD * (T_TOK/2)];
__device__ __align__(16) __half   g_h16[(size_t)T_TOK * HID];
__device__ __align__(16) __half   g_wqkv16[(size_t)HID * QKV_W];
__device__ __align__(16) __half   g_wo16[(size_t)OUT_W * HID];
__device__ __align__(16) __half   g_attn16[(size_t)T_TOK * OUT_W];
__device__ __align__(16) float2   g_rope[(size_t)T_TOK * 64];   // (cos,sin) per (t,i)
__device__ float g_invfreq_pi[HD/2];

// ---------------------------------------------------------------------------
// helpers
// ---------------------------------------------------------------------------
__device__ __forceinline__ unsigned packh2(float x, float y) {
    __half2 h = __floats2half2_rn(x, y);
    return *(unsigned*)&h;
}

__device__ __forceinline__ void split2(float x, float y, unsigned& hi, unsigned& lo) {
    __half hx = __float2half_rn(x);
    __half hy = __float2half_rn(y);
    float rx = x - __half2float(hx);
    float ry = y - __half2float(hy);
    hi = (unsigned)__half_as_ushort(hx) | ((unsigned)__half_as_ushort(hy) << 16);
    lo = (unsigned)__half_as_ushort(__float2half_rn(rx)) |
         ((unsigned)__half_as_ushort(__float2half_rn(ry)) << 16);
}

__device__ __forceinline__ void mma16(float c[4], unsigned a0, unsigned a1,
                                      unsigned a2, unsigned a3,
                                      unsigned b0, unsigned b1) {
    asm volatile(
        "mma.sync.aligned.m16n8k16.row.col.f32.f16.f16.f32 "
        "{%0,%1,%2,%3}, {%4,%5,%6,%7}, {%8,%9}, {%0,%1,%2,%3};\n"
        : "+f"(c[0]), "+f"(c[1]), "+f"(c[2]), "+f"(c[3])
        : "r"(a0), "r"(a1), "r"(a2), "r"(a3), "r"(b0), "r"(b1));
}

__device__ __forceinline__ unsigned smem_u32(const void* p) {
    return (unsigned)__cvta_generic_to_shared(p);
}

__device__ __forceinline__ void ldsm_x4(unsigned& r0, unsigned& r1,
                                        unsigned& r2, unsigned& r3,
                                        unsigned addr) {
    asm volatile("ldmatrix.sync.aligned.m8n8.x4.shared.b16 {%0,%1,%2,%3}, [%4];\n"
                 : "=r"(r0), "=r"(r1), "=r"(r2), "=r"(r3) : "r"(addr));
}

__device__ __forceinline__ void ldsm_x4_t(unsigned& r0, unsigned& r1,
                                          unsigned& r2, unsigned& r3,
                                          unsigned addr) {
    asm volatile("ldmatrix.sync.aligned.m8n8.x4.trans.shared.b16 {%0,%1,%2,%3}, [%4];\n"
                 : "=r"(r0), "=r"(r1), "=r"(r2), "=r"(r3) : "r"(addr));
}

#define CP16(dst, src) \
    asm volatile("cp.async.cg.shared.global [%0], [%1], 16;\n" \
                 :: "r"(dst), "l"(src))
#define CP16A(dst, src) \
    asm volatile("cp.async.ca.shared.global [%0], [%1], 16;\n" \
                 :: "r"(dst), "l"(src))
#define CPCOMMIT() asm volatile("cp.async.commit_group;\n")
#define CPWAIT0()  asm volatile("cp.async.wait_group 0;\n")
#define CPWAIT1()  asm volatile("cp.async.wait_group 1;\n")

// ---------------------------------------------------------------------------
// small kernels
// ---------------------------------------------------------------------------
__global__ void init_invfreq_kernel() {
    int i = threadIdx.x;
    double inv = pow(1.0e6, -((double)(2 * i)) / 128.0);
    g_invfreq_pi[i] = (float)(inv / 3.14159265358979323846);
}

// RoPE trig table: one (cos,sin) per (token, freq)
__global__ void rope_table_kernel(const int* __restrict__ positions) {
    int t = blockIdx.x;
    int i = threadIdx.x;   // 0..63
    float pos = (float)positions[t];
    float f = pos * g_invfreq_pi[i];
    g_rope[t * 64 + i] = make_float2(cospif(f), sinpif(f));
}

__global__ void conv_f16_kernel(const float4* __restrict__ src,
                                uint2* __restrict__ dst, int n4) {
    int i = blockIdx.x * blockDim.x + threadIdx.x;
    if (i < n4) {
        float4 v = src[i];
        dst[i] = make_uint2(packh2(v.x, v.y), packh2(v.z, v.w));
    }
}

// V transpose (hi plane only — V-lo term dropped, error ~2.8e-4 in quadrature)
__global__ __launch_bounds__(256) void prep_v_kernel(const float* __restrict__ qkv) {
    __shared__ float Vs[64 * 133];
    int bt = blockIdx.x;
    int hk = blockIdx.y;
    int tid = threadIdx.x;
    const float* vb = qkv + (size_t)bt * 64 * QKV_W + (NH + NKV) * HD + hk * HD;
#pragma unroll
    for (int it = 0; it < 8; it++) {
        int idx = tid + it * 256;
        int r = idx >> 5;
        int c4 = (idx & 31) * 4;
        float4 v = *(const float4*)(vb + (size_t)r * QKV_W + c4);
        Vs[r * 133 + c4 + 0] = v.x;
        Vs[r * 133 + c4 + 1] = v.y;
        Vs[r * 133 + c4 + 2] = v.z;
        Vs[r * 133 + c4 + 3] = v.w;
    }
    __syncthreads();
#pragma unroll
    for (int it = 0; it < 16; it++) {
        int d = it * 8 + (tid >> 5);
        int jw = tid & 31;
        float v0 = Vs[(2 * jw) * 133 + d];
        float v1 = Vs[(2 * jw + 1) * 133 + d];
        size_t w = (size_t)(hk * 128 + d) * (T_TOK / 2) + bt * 32 + jw;
        g_VTh[w] = packh2(v0, v1);
    }
}

// ---------------------------------------------------------------------------
// fp16 HGEMM: 128x128 tile, BK=64, 8 warps (2x4 -> 64x32 per warp),
// 3-stage cp.async ring (wait_group 1), dynamic smem (107.5 KB).
// FUSED=true: QKV epilogue (RoPE+split for Q/K cols, fp32 store for V cols).
// ---------------------------------------------------------------------------
#define GA_STR 72
#define GB_STR 136
#define HG_STAGES 3
#define HG_A_HALVES (128 * GA_STR)
#define HG_B_HALVES (64 * GB_STR)
#define HG_STAGE_HALVES (HG_A_HALVES + HG_B_HALVES)
#define HG_SMEM_BYTES (HG_STAGES * HG_STAGE_HALVES * 2)   // 107520

template <bool FUSED>
__global__ __launch_bounds__(256) void hgemm_t(const __half* __restrict__ A,
                                               const __half* __restrict__ B,
                                               float* __restrict__ C,
                                               int M, int N, int K) {
    extern __shared__ __half hsm[];

    int tid = threadIdx.x;
    int warp = tid >> 5;
    int lane = tid & 31;
    int wm = warp >> 2;
    int wn = warp & 3;
    int m_warp = wm * 64;
    int n_warp = wn * 32;
    int gid = lane >> 2;
    int tig = lane & 3;
    int lrow = (lane & 7) + ((lane >> 3) & 1) * 8;
    int lcol8 = (lane >> 4) * 8;

    const __half* Ab = A + (size_t)blockIdx.y * 128 * K;
    const __half* Bb = B + (size_t)blockIdx.x * 128;
    float* Cb = C + (size_t)blockIdx.y * 128 * N + (size_t)blockIdx.x * 128;

    float acc[4][4][4];
#pragma unroll
    for (int mt = 0; mt < 4; mt++)
#pragma unroll
        for (int ng = 0; ng < 4; ng++)
#pragma unroll
            for (int q = 0; q < 4; q++) acc[mt][ng][q] = 0.f;

    int NC = K / 64;

    auto stage_commit = [&](int i) {
        if (i < NC) {
            __half* As = hsm + (i % HG_STAGES) * HG_STAGE_HALVES;
            __half* Bs = As + HG_A_HALVES;
            int k0 = i * 64;
#pragma unroll
            for (int it = 0; it < 4; it++) {
                int idx = tid + it * 256;
                int r = idx >> 3;
                int c8 = (idx & 7) * 8;
                CP16(smem_u32(As + r * GA_STR + c8),
                     Ab + (size_t)r * K + k0 + c8);
            }
#pragma unroll
            for (int it = 0; it < 4; it++) {
                int idx = tid + it * 256;
                int r = idx >> 4;
                int c8 = (idx & 15) * 8;
                CP16(smem_u32(Bs + r * GB_STR + c8),
                     Bb + (size_t)(k0 + r) * N + c8);
            }
        }
        CPCOMMIT();
    };

    stage_commit(0);
    stage_commit(1);

    for (int i = 0; i < NC; i++) {
        CPWAIT1();
        __syncthreads();
        stage_commit(i + 2);

        const __half* Ac = hsm + (i % HG_STAGES) * HG_STAGE_HALVES;
        const __half* Bc = Ac + HG_A_HALVES;
#pragma unroll
        for (int ks = 0; ks < 64; ks += 16) {
            unsigned bf[2][4];
#pragma unroll
            for (int nt = 0; nt < 2; nt++) {
                ldsm_x4_t(bf[nt][0], bf[nt][1], bf[nt][2], bf[nt][3],
                          smem_u32(Bc + (ks + lrow) * GB_STR + n_warp + nt * 16 + lcol8));
            }
#pragma unroll
            for (int mt = 0; mt < 4; mt++) {
                unsigned a0, a1, a2, a3;
                ldsm_x4(a0, a1, a2, a3,
                        smem_u32(Ac + (m_warp + mt * 16 + lrow) * GA_STR + ks + lcol8));
                mma16(acc[mt][0], a0, a1, a2, a3, bf[0][0], bf[0][1]);
                mma16(acc[mt][1], a0, a1, a2, a3, bf[0][2], bf[0][3]);
                mma16(acc[mt][2], a0, a1, a2, a3, bf[1][0], bf[1][1]);
                mma16(acc[mt][3], a0, a1, a2, a3, bf[1][2], bf[1][3]);
            }
        }
    }

    // ---- epilogue ----
    int col0 = blockIdx.x * 128;
    bool fused_blk = FUSED && (col0 < (NH + NKV) * HD);
    if (!fused_blk) {
#pragma unroll
        for (int mt = 0; mt < 4; mt++) {
#pragma unroll
            for (int ng = 0; ng < 4; ng++) {
                int row0 = m_warp + mt * 16 + gid;
                int col  = n_warp + ng * 8 + tig * 2;
                *(float2*)(Cb + (size_t)row0 * N + col) =
                    make_float2(acc[mt][ng][0], acc[mt][ng][1]);
                *(float2*)(Cb + (size_t)(row0 + 8) * N + col) =
                    make_float2(acc[mt][ng][2], acc[mt][ng][3]);
            }
        }
    } else {
        bool isQ = (col0 < NH * HD);
        int tbase = blockIdx.y * 128;
#pragma unroll
        for (int mt = 0; mt < 4; mt++) {
#pragma unroll
            for (int ng = 0; ng < 4; ng++) {
                int t0 = tbase + m_warp + mt * 16 + gid;
                int t1 = t0 + 8;
                int col = col0 + n_warp + ng * 8 + tig * 2;   // even
                int i = (col & 127) >> 1;
                float2 cs0 = g_rope[t0 * 64 + i];
                float2 cs1 = g_rope[t1 * 64 + i];
                float x1a = acc[mt][ng][0], x2a = acc[mt][ng][1];
                float x1b = acc[mt][ng][2], x2b = acc[mt][ng][3];
                float o1a = x1a * cs0.x - x2a * cs0.y;
                float o2a = x2a * cs0.x + x1a * cs0.y;
                float o1b = x1b * cs1.x - x2b * cs1.y;
                float o2b = x2b * cs1.x + x1b * cs1.y;
                unsigned hiA, loA, hiB, loB;
                if (isQ) {
                    o1a *= SM_SCALE; o2a *= SM_SCALE;
                    o1b *= SM_SCALE; o2b *= SM_SCALE;
                    split2(o1a, o2a, hiA, loA);
                    split2(o1b, o2b, hiB, loB);
                    int w = col >> 1;
                    g_Qh[(size_t)t0 * 2048 + w] = hiA;
                    g_Ql[(size_t)t0 * 2048 + w] = loA;
                    g_Qh[(size_t)t1 * 2048 + w] = hiB;
                    g_Ql[(size_t)t1 * 2048 + w] = loB;
                } else {
                    split2(o1a, o2a, hiA, loA);
                    split2(o1b, o2b, hiB, loB);
                    int w = (col - NH * HD) >> 1;
                    g_Kh[(size_t)t0 * 512 + w] = hiA;
                    g_Kl[(size_t)t0 * 512 + w] = loA;
                    g_Kh[(size_t)t1 * 512 + w] = hiB;
                    g_Kl[(size_t)t1 * 512 + w] = loB;
                }
            }
        }
    }
}

// ---------------------------------------------------------------------------
// Flash attention v5: BQ=64, 128 threads, 2 CTAs/SM.
// - P.V A-fragments from registers.
// - V hi-plane only (lo term dropped).
// - Split commit groups: VT load overlaps S+softmax compute.
// smem: QH[2][64][68] + KH[2][64][68] + VT0[128][36] = 88 KB.
// ---------------------------------------------------------------------------
#define QK_STR 68
#define VT_STR 36

#define QH0_OFF 0
#define QH1_OFF (64*QK_STR)
#define KH0_OFF (QH1_OFF + 64*QK_STR)
#define KH1_OFF (KH0_OFF + 64*QK_STR)
#define VT0_OFF (KH1_OFF + 64*QK_STR)
#define FLASH_SMEM_WORDS (VT0_OFF + 128*VT_STR)   // 22016
#define FLASH_SMEM_BYTES (FLASH_SMEM_WORDS * 4)   // 88064

__global__ __launch_bounds__(128) void flash16_kernel(__half* __restrict__ out16) {
    extern __shared__ unsigned sw[];
    unsigned* QH0 = sw + QH0_OFF;
    unsigned* QH1 = sw + QH1_OFF;
    unsigned* KH0 = sw + KH0_OFF;
    unsigned* KH1 = sw + KH1_OFF;
    unsigned* VT0 = sw + VT0_OFF;

    int qb = gridDim.x - 1 - blockIdx.x;
    int hq = blockIdx.y;
    int hk = hq >> 2;
    int tid = threadIdx.x;
    int warp = tid >> 5;
    int lane = tid & 31;
    int gid = lane >> 2;
    int tig = lane & 3;
    int m0 = warp * 16;

    int lrow  = (lane & 7) + ((lane >> 3) & 1) * 8;
    int acol4 = ((lane >> 4) & 1) * 4;
    int krow  = (lane & 7) + ((lane >> 4) & 1) * 8;
    int kcol4 = ((lane >> 3) & 1) * 4;

    // ---- stage Q (cp.async, once) ----
#pragma unroll
    for (int it = 0; it < 8; it++) {
        int idx = tid + it * 128;
        int r = idx >> 4;
        int c = (idx & 15) * 4;
        const unsigned* s0 = g_Qh + (size_t)(qb * 64 + r) * 2048 + hq * 64 + c;
        const unsigned* s1 = g_Ql + (size_t)(qb * 64 + r) * 2048 + hq * 64 + c;
        CP16A(smem_u32(QH0 + r * QK_STR + c), s0);
        CP16A(smem_u32(QH1 + r * QK_STR + c), s1);
    }

    float mprev0 = -1e30f, mprev1 = -1e30f;
    float lsum0 = 0.f, lsum1 = 0.f;
    float acco[16][4];
#pragma unroll
    for (int dt = 0; dt < 16; dt++)
#pragma unroll
        for (int q = 0; q < 4; q++) acco[dt][q] = 0.f;

    int grow0 = qb * 64 + m0 + gid;
    int grow1 = grow0 + 8;

    int nkt = qb + 1;
    for (int kt = 0; kt < nkt; kt++) {
        __syncthreads();   // previous iteration's consumers done

        // ---- stage K (group 1) ----
#pragma unroll
        for (int it = 0; it < 8; it++) {
            int idx = tid + it * 128;
            int r = idx >> 4;
            int c = (idx & 15) * 4;
            const unsigned* s0 = g_Kh + (size_t)(kt * 64 + r) * 512 + hk * 64 + c;
            const unsigned* s1 = g_Kl + (size_t)(kt * 64 + r) * 512 + hk * 64 + c;
            CP16A(smem_u32(KH0 + r * QK_STR + c), s0);
            CP16A(smem_u32(KH1 + r * QK_STR + c), s1);
        }
        CPCOMMIT();
        // ---- stage VT hi plane (group 2, overlaps S+softmax) ----
#pragma unroll
        for (int it = 0; it < 8; it++) {
            int idx = tid + it * 128;
            int r = idx >> 3;
            int c = (idx & 7) * 4;
            const unsigned* s0 = g_VTh + (size_t)(hk * 128 + r) * (T_TOK/2) + kt * 32 + c;
            CP16A(smem_u32(VT0 + r * VT_STR + c), s0);
        }
        CPCOMMIT();

        CPWAIT1();         // K complete (VT may still be in flight)
        __syncthreads();

        // ---- S = Q K^T (3x fp16 split) via ldmatrix ----
        float accs[8][4];
#pragma unroll
        for (int nt = 0; nt < 8; nt++)
#pragma unroll
            for (int q = 0; q < 4; q++) accs[nt][q] = 0.f;

#pragma unroll
        for (int ks = 0; ks < 8; ks++) {
            unsigned ah[4], al[4];
            ldsm_x4(ah[0], ah[1], ah[2], ah[3],
                    smem_u32(QH0 + (m0 + lrow) * QK_STR + ks * 8 + acol4));
            ldsm_x4(al[0], al[1], al[2], al[3],
                    smem_u32(QH1 + (m0 + lrow) * QK_STR + ks * 8 + acol4));
#pragma unroll
            for (int nt2 = 0; nt2 < 4; nt2++) {
                unsigned bh[4], bl[4];
                ldsm_x4(bh[0], bh[1], bh[2], bh[3],
                        smem_u32(KH0 + (nt2 * 16 + krow) * QK_STR + ks * 8 + kcol4));
                ldsm_x4(bl[0], bl[1], bl[2], bl[3],
                        smem_u32(KH1 + (nt2 * 16 + krow) * QK_STR + ks * 8 + kcol4));
                mma16(accs[2*nt2],   ah[0], ah[1], ah[2], ah[3], bh[0], bh[1]);
                mma16(accs[2*nt2],   ah[0], ah[1], ah[2], ah[3], bl[0], bl[1]);
                mma16(accs[2*nt2],   al[0], al[1], al[2], al[3], bh[0], bh[1]);
                mma16(accs[2*nt2+1], ah[0], ah[1], ah[2], ah[3], bh[2], bh[3]);
                mma16(accs[2*nt2+1], ah[0], ah[1], ah[2], ah[3], bl[2], bl[3]);
                mma16(accs[2*nt2+1], al[0], al[1], al[2], al[3], bh[2], bh[3]);
            }
        }

        // ---- causal mask + online softmax ----
        int colb = kt * 64 + 2 * tig;
        float mx0 = -1e30f, mx1 = -1e30f;
#pragma unroll
        for (int nt = 0; nt < 8; nt++) {
            int c0 = colb + nt * 8;
            int c1 = c0 + 1;
            accs[nt][0] = (c0 <= grow0) ? accs[nt][0] : -1e30f;
            accs[nt][1] = (c1 <= grow0) ? accs[nt][1] : -1e30f;
            accs[nt][2] = (c0 <= grow1) ? accs[nt][2] : -1e30f;
            accs[nt][3] = (c1 <= grow1) ? accs[nt][3] : -1e30f;
            mx0 = fmaxf(mx0, fmaxf(accs[nt][0], accs[nt][1]));
            mx1 = fmaxf(mx1, fmaxf(accs[nt][2], accs[nt][3]));
        }
        mx0 = fmaxf(mx0, __shfl_xor_sync(0xffffffffu, mx0, 1));
        mx0 = fmaxf(mx0, __shfl_xor_sync(0xffffffffu, mx0, 2));
        mx1 = fmaxf(mx1, __shfl_xor_sync(0xffffffffu, mx1, 1));
        mx1 = fmaxf(mx1, __shfl_xor_sync(0xffffffffu, mx1, 2));

        float mn0 = fmaxf(mprev0, mx0);
        float mn1 = fmaxf(mprev1, mx1);
        float corr0 = __expf(mprev0 - mn0);
        float corr1 = __expf(mprev1 - mn1);
        mprev0 = mn0;
        mprev1 = mn1;

        float sum0 = 0.f, sum1 = 0.f;
#pragma unroll
        for (int nt = 0; nt < 8; nt++) {
            accs[nt][0] = __expf(accs[nt][0] - mn0);
            accs[nt][1] = __expf(accs[nt][1] - mn0);
            accs[nt][2] = __expf(accs[nt][2] - mn1);
            accs[nt][3] = __expf(accs[nt][3] - mn1);
            sum0 += accs[nt][0] + accs[nt][1];
            sum1 += accs[nt][2] + accs[nt][3];
        }
        sum0 += __shfl_xor_sync(0xffffffffu, sum0, 1);
        sum0 += __shfl_xor_sync(0xffffffffu, sum0, 2);
        sum1 += __shfl_xor_sync(0xffffffffu, sum1, 1);
        sum1 += __shfl_xor_sync(0xffffffffu, sum1, 2);
        lsum0 = lsum0 * corr0 + sum0;
        lsum1 = lsum1 * corr1 + sum1;

#pragma unroll
        for (int dt = 0; dt < 16; dt++) {
            acco[dt][0] *= corr0;
            acco[dt][1] *= corr0;
            acco[dt][2] *= corr1;
            acco[dt][3] *= corr1;
        }

        CPWAIT0();         // VT complete
        __syncthreads();   // VT visible to all warps

        // ---- O += P V (Vh only): A-fragments from registers ----
#pragma unroll
        for (int kb = 0; kb < 4; kb++) {
            unsigned ah0, al0, ah1, al1, ah2, al2, ah3, al3;
            split2(accs[2*kb][0],   accs[2*kb][1],   ah0, al0);
            split2(accs[2*kb][2],   accs[2*kb][3],   ah1, al1);
            split2(accs[2*kb+1][0], accs[2*kb+1][1], ah2, al2);
            split2(accs[2*kb+1][2], accs[2*kb+1][3], ah3, al3);
#pragma unroll
            for (int dt2 = 0; dt2 < 8; dt2++) {
                unsigned vh[4];
                ldsm_x4(vh[0], vh[1], vh[2], vh[3],
                        smem_u32(VT0 + (dt2 * 16 + krow) * VT_STR + kb * 8 + kcol4));
                mma16(acco[2*dt2],   ah0, ah1, ah2, ah3, vh[0], vh[1]);
                mma16(acco[2*dt2],   al0, al1, al2, al3, vh[0], vh[1]);
                mma16(acco[2*dt2+1], ah0, ah1, ah2, ah3, vh[2], vh[3]);
                mma16(acco[2*dt2+1], al0, al1, al2, al3, vh[2], vh[3]);
            }
        }
    }

    // ---- epilogue: write attn as fp16 ----
    float il0 = 1.0f / lsum0;
    float il1 = 1.0f / lsum1;
    __half* o0 = out16 + (size_t)grow0 * OUT_W + hq * HD;
    __half* o1 = out16 + (size_t)grow1 * OUT_W + hq * HD;
#pragma unroll
    for (int dt = 0; dt < 16; dt++) {
        int col = dt * 8 + 2 * tig;
        *(unsigned*)(o0 + col) = packh2(acco[dt][0] * il0, acco[dt][1] * il0);
        *(unsigned*)(o1 + col) = packh2(acco[dt][2] * il1, acco[dt][3] * il1);
    }
}

// ---------------------------------------------------------------------------
// launch
// ---------------------------------------------------------------------------
extern "C" void kernel_launch(void* const* d_in, const int* in_sizes, int n_in,
                              void* d_out, int out_size) {
    (void)in_sizes; (void)n_in; (void)out_size;
    const int*   positions = (const int*)d_in[0];
    const float* hidden    = (const float*)d_in[1];
    const float* Wqkv      = (const float*)d_in[2];
    const float* Wo        = (const float*)d_in[3];
    float*       out       = (float*)d_out;

    void *qkv_p, *h16_p, *wqkv16_p, *wo16_p, *attn16_p;
    cudaGetSymbolAddress(&qkv_p, g_qkv);
    cudaGetSymbolAddress(&h16_p, g_h16);
    cudaGetSymbolAddress(&wqkv16_p, g_wqkv16);
    cudaGetSymbolAddress(&wo16_p, g_wo16);
    cudaGetSymbolAddress(&attn16_p, g_attn16);
    float*  qkv    = (float*)qkv_p;
    __half* h16    = (__half*)h16_p;
    __half* wqkv16 = (__half*)wqkv16_p;
    __half* wo16   = (__half*)wo16_p;
    __half* attn16 = (__half*)attn16_p;

    cudaFuncSetAttribute(flash16_kernel,
                         cudaFuncAttributeMaxDynamicSharedMemorySize,
                         FLASH_SMEM_BYTES);
    cudaFuncSetAttribute(hgemm_t<true>,
                         cudaFuncAttributeMaxDynamicSharedMemorySize,
                         HG_SMEM_BYTES);
    cudaFuncSetAttribute(hgemm_t<false>,
                         cudaFuncAttributeMaxDynamicSharedMemorySize,
                         HG_SMEM_BYTES);

    init_invfreq_kernel<<<1, 64>>>();
    rope_table_kernel<<<T_TOK, 64>>>(positions);

    // fp32 -> fp16 conversions
    {
        int n4 = T_TOK * HID / 4;
        conv_f16_kernel<<<(n4 + 255) / 256, 256>>>((const float4*)hidden,
                                                   (uint2*)h16, n4);
        n4 = HID * QKV_W / 4;
        conv_f16_kernel<<<(n4 + 255) / 256, 256>>>((const float4*)Wqkv,
                                                   (uint2*)wqkv16, n4);
        n4 = OUT_W * HID / 4;
        conv_f16_kernel<<<(n4 + 255) / 256, 256>>>((const float4*)Wo,
                                                   (uint2*)wo16, n4);
    }

    // qkv = hidden @ Wqkv — fused RoPE+split epilogue for Q/K, fp32 V
    hgemm_t<true><<<dim3(QKV_W / 128, T_TOK / 128), 256, HG_SMEM_BYTES>>>(
        h16, wqkv16, qkv, T_TOK, QKV_W, HID);

    // V transpose (hi plane)
    prep_v_kernel<<<dim3(T_TOK / 64, NKV), 256>>>(qkv);

    // flash attention (BQ=64, 2 CTAs/SM, VT-load overlap)
    flash16_kernel<<<dim3(T_TOK / 64, NH), 128, FLASH_SMEM_BYTES>>>(attn16);

    // out = attn @ Wo
    hgemm_t<false><<<dim3(HID / 128, T_TOK / 128), 256, HG_SMEM_BYTES>>>(
        attn16, wo16, out, T_TOK, HID, HID);
}